// round 3
// baseline (speedup 1.0000x reference)
#include <cuda_runtime.h>

#define UNITS 224
#define SENS  64
#define MOTORN 32
#define CMDN  64
#define INTERN 128
#define OUTL  32
#define NB    32
#define NT    32
#define UNF   6
#define CAPR  128      // recurrent synapses per post (cap)
#define CAPS  32       // sensory synapses per post (cap)
#define NTHREADS 384
#define LOG2E 1.4426950408889634f
#define EPSF  1e-8f

// Compacted per-post synapse tables (prep writes each launch; deterministic).
__device__ float4 g_rsyn[UNITS * CAPR];  // {a=sig*log2e, b=sig*mu*log2e, wm, wm*erev}
__device__ int    g_ridx[UNITS * CAPR];  // presynaptic index MINUS 32 (vtraj index)
__device__ int    g_rcnt[UNITS];         // -1 => structure/cap violation
__device__ float4 g_ssyn[UNITS * CAPS];
__device__ int    g_sidx[UNITS * CAPS];  // sensory index 0..63
__device__ int    g_scnt[UNITS];         // -1 => cap violation

__device__ __forceinline__ float ex2f(float x) {
    float r; asm("ex2.approx.ftz.f32 %0, %1;" : "=f"(r) : "f"(x)); return r;
}
__device__ __forceinline__ float rcpf(float x) {
    float r; asm("rcp.approx.ftz.f32 %0, %1;" : "=f"(r) : "f"(x)); return r;
}
__device__ __forceinline__ void barn(int id, int cnt) {
    asm volatile("bar.sync %0, %1;" :: "r"(id), "r"(cnt) : "memory");
}

// One warp per post column; ballot-based compaction + structure validation.
// Structure required by the fast path:
//   * every recurrent pre-index >= 32 (no motor as presynaptic)
//   * posts 96..223 (inter) receive zero recurrent synapses
__global__ void prep_kernel(
    const float* __restrict__ smu,  const float* __restrict__ ssig,
    const float* __restrict__ swt,  const float* __restrict__ serev,
    const float* __restrict__ smask,
    const float* __restrict__ mu,   const float* __restrict__ sig,
    const float* __restrict__ wt,   const float* __restrict__ erev,
    const float* __restrict__ mask)
{
    const int j    = blockIdx.x;
    const int lane = threadIdx.x;
    const unsigned FULL = 0xffffffffu;
    const unsigned ltmask = (1u << lane) - 1u;

    int cnt = 0, bad = 0;
    for (int i0 = 0; i0 < UNITS; i0 += 32) {
        const int i = i0 + lane;
        const int gi = i * UNITS + j;
        float m = mask[gi];
        unsigned bal = __ballot_sync(FULL, m != 0.f);
        if (m != 0.f) {
            int pos = cnt + __popc(bal & ltmask);
            if (pos < CAPR) {
                float sg = sig[gi];
                float wm = wt[gi] * m;
                g_rsyn[j * CAPR + pos] =
                    make_float4(sg * LOG2E, sg * mu[gi] * LOG2E, wm, wm * erev[gi]);
                g_ridx[j * CAPR + pos] = i - 32;
            }
            if (i < 32) bad = 1;          // motor presynaptic not supported fast
        }
        cnt += __popc(bal);
    }
    if (cnt > CAPR) bad = 1;
    if (j >= MOTORN + CMDN && cnt > 0) bad = 1;   // inter must be recurrent-free
    bad = (__ballot_sync(FULL, bad) != 0u);
    if (lane == 0) g_rcnt[j] = bad ? -1 : cnt;

    cnt = 0; bad = 0;
    for (int i0 = 0; i0 < SENS; i0 += 32) {
        const int i = i0 + lane;
        const int gi = i * UNITS + j;
        float m = smask[gi];
        unsigned bal = __ballot_sync(FULL, m != 0.f);
        if (m != 0.f) {
            int pos = cnt + __popc(bal & ltmask);
            if (pos < CAPS) {
                float sg = ssig[gi];
                float wm = swt[gi] * m;
                g_ssyn[j * CAPS + pos] =
                    make_float4(sg * LOG2E, sg * smu[gi] * LOG2E, wm, wm * serev[gi]);
                g_sidx[j * CAPS + pos] = i;
            }
            cnt += 0;
        }
        cnt += __popc(bal);
    }
    if (cnt > CAPS) bad = 1;
    bad = (__ballot_sync(FULL, bad) != 0u);
    if (lane == 0) g_scnt[j] = bad ? -1 : cnt;
}

__global__ void __launch_bounds__(NTHREADS)
ncp_kernel(
    const float* __restrict__ inputs,
    const float* __restrict__ input_w, const float* __restrict__ input_b,
    const float* __restrict__ smu,  const float* __restrict__ ssig,
    const float* __restrict__ swt,  const float* __restrict__ serev,
    const float* __restrict__ smask,
    const float* __restrict__ mu,   const float* __restrict__ sig,
    const float* __restrict__ wt,   const float* __restrict__ erev,
    const float* __restrict__ mask,
    const float* __restrict__ gleak, const float* __restrict__ vleak,
    const float* __restrict__ cm,
    const float* __restrict__ output_w, const float* __restrict__ output_b,
    const float* __restrict__ dense_w,  const float* __restrict__ dense_b,
    float* __restrict__ out)
{
    __shared__ float vtraj[UNF][UNITS - MOTORN];  // [u][pre-32], pre in [32,224)
    __shared__ float sx[SENS];
    __shared__ float smv[MOTORN];
    __shared__ float sdw[MOTORN * OUTL];
    __shared__ float sdb[OUTL];
    __shared__ float vsh0[UNITS], vsh1[UNITS];    // fallback only
    __shared__ int   sbad;

    const int t = threadIdx.x;
    const int b = blockIdx.x;

    if (t == 0) sbad = 0;
    for (int i = t; i < MOTORN * OUTL; i += NTHREADS) sdw[i] = dense_w[i];
    if (t < OUTL) sdb[t] = dense_b[t];
    if (t < UNITS) { if (g_rcnt[t] < 0 || g_scnt[t] < 0) sbad = 1; }
    __syncthreads();

    if (!sbad) {
        // ================= FAST PATH (layered wiring) =================
        const bool is_cmd = (t < 256);
        // command role
        int   cpost = 0, ch = 0, crcnt = 0, cscnt = 0;
        float ccmt = 0.f, cgl = 0.f, cgv = 0.f;
        // inter+motor role
        int   ipost = 0, it2 = 0, iscnt = 0;
        float icmt = 0.f, igl = 0.f, igv = 0.f;
        int   mpost = 0, mh = 0, mrcnt = 0, mscnt = 0;
        float mcmt = 0.f, mgl = 0.f, mgv = 0.f, mow = 0.f, mob = 0.f;

        if (is_cmd) {
            cpost = MOTORN + (t >> 2); ch = t & 3;
            ccmt = cm[cpost] * (float)UNF;
            cgl  = gleak[cpost]; cgv = cgl * vleak[cpost];
            crcnt = g_rcnt[cpost]; cscnt = g_scnt[cpost];
        } else {
            it2 = t - 256;
            ipost = MOTORN + CMDN + it2;
            icmt = cm[ipost] * (float)UNF;
            igl  = gleak[ipost]; igv = igl * vleak[ipost];
            iscnt = g_scnt[ipost];
            mpost = it2 >> 2; mh = it2 & 3;
            mcmt = cm[mpost] * (float)UNF;
            mgl  = gleak[mpost]; mgv = mgl * vleak[mpost];
            mrcnt = g_rcnt[mpost]; mscnt = g_scnt[mpost];
            mow = output_w[mpost]; mob = output_b[mpost];
        }
        float vc = 0.f, vi = 0.f, vm = 0.f;

        if (t < SENS)
            sx[t] = fmaf(inputs[(b * NT) * SENS + t], input_w[t], input_b[t]);
        __syncthreads();

        for (int s = 0; s < NT; s++) {
            float cnum = 0.f, cden = 0.f;     // cmd per-step bases
            float mnum = 0.f, mden = 0.f;     // motor per-step bases
            if (is_cmd) {
                if (ch == 0) vtraj[0][cpost - MOTORN] = vc;
                float sn = 0.f, sd = 0.f;     // usually cscnt == 0
                for (int k = 0; k < cscnt; k++) {
                    float4 sy = g_ssyn[cpost * CAPS + k];
                    float x = sx[g_sidx[cpost * CAPS + k]];
                    float sg = rcpf(1.f + ex2f(fmaf(-sy.x, x, sy.y)));
                    sd = fmaf(sy.z, sg, sd); sn = fmaf(sy.w, sg, sn);
                }
                cnum = cgv + sn;
                cden = ccmt + cgl + sd + EPSF;
            } else {
                // ---- inter: sensory sums + full 6-unfold trajectory ----
                float sn = 0.f, sd = 0.f;
#pragma unroll 4
                for (int k = 0; k < iscnt; k++) {
                    float4 sy = g_ssyn[ipost * CAPS + k];
                    float x = sx[g_sidx[ipost * CAPS + k]];
                    float sg = rcpf(1.f + ex2f(fmaf(-sy.x, x, sy.y)));
                    sd = fmaf(sy.z, sg, sd); sn = fmaf(sy.w, sg, sn);
                }
                const float num  = igv + sn;
                const float dinv = rcpf(icmt + igl + sd + EPSF);
                vtraj[0][CMDN + it2] = vi;
#pragma unroll
                for (int u = 1; u <= UNF; u++) {
                    vi = fmaf(icmt, vi, num) * dinv;
                    if (u < UNF) vtraj[u][CMDN + it2] = vi;
                }
                // ---- motor per-step bases (usually mscnt == 0) ----
                float snm = 0.f, sdm = 0.f;
                for (int k = 0; k < mscnt; k++) {
                    float4 sy = g_ssyn[mpost * CAPS + k];
                    float x = sx[g_sidx[mpost * CAPS + k]];
                    float sg = rcpf(1.f + ex2f(fmaf(-sy.x, x, sy.y)));
                    sdm = fmaf(sy.z, sg, sdm); snm = fmaf(sy.w, sg, snm);
                }
                mnum = mgv + snm;
                mden = mcmt + mgl + sdm + EPSF;
            }
            __syncthreads();   // inter trajectory + vtraj[0] published

            if (is_cmd) {
                const float4* __restrict__ syn = &g_rsyn[cpost * CAPR];
                const int*    __restrict__ idx = &g_ridx[cpost * CAPR];
#pragma unroll
                for (int u = 1; u <= UNF; u++) {
                    const float* __restrict__ vrow = &vtraj[u - 1][0];
                    float na = 0.f, da = 0.f;
#pragma unroll 4
                    for (int k = ch; k < crcnt; k += 4) {
                        float4 sy = syn[k];
                        float vp = vrow[idx[k]];
                        float sg = rcpf(1.f + ex2f(fmaf(-sy.x, vp, sy.y)));
                        da = fmaf(sy.z, sg, da);
                        na = fmaf(sy.w, sg, na);
                    }
                    na += __shfl_xor_sync(0xffffffffu, na, 1);
                    na += __shfl_xor_sync(0xffffffffu, na, 2);
                    da += __shfl_xor_sync(0xffffffffu, da, 1);
                    da += __shfl_xor_sync(0xffffffffu, da, 2);
                    vc = (fmaf(ccmt, vc, cnum) + na) * rcpf(cden + da);
                    if (u < UNF) {
                        if (ch == 0) vtraj[u][cpost - MOTORN] = vc;
                        barn(1, 256);
                    }
                }
            }
            __syncthreads();   // command trajectory complete

            if (!is_cmd) {
                // ---- motor: 6 unfolds from stored command trajectory ----
                const float4* __restrict__ syn = &g_rsyn[mpost * CAPR];
                const int*    __restrict__ idx = &g_ridx[mpost * CAPR];
#pragma unroll
                for (int u = 1; u <= UNF; u++) {
                    const float* __restrict__ vrow = &vtraj[u - 1][0];
                    float na = 0.f, da = 0.f;
#pragma unroll 4
                    for (int k = mh; k < mrcnt; k += 4) {
                        float4 sy = syn[k];
                        float vp = vrow[idx[k]];
                        float sg = rcpf(1.f + ex2f(fmaf(-sy.x, vp, sy.y)));
                        da = fmaf(sy.z, sg, da);
                        na = fmaf(sy.w, sg, na);
                    }
                    na += __shfl_xor_sync(0xffffffffu, na, 1);
                    na += __shfl_xor_sync(0xffffffffu, na, 2);
                    da += __shfl_xor_sync(0xffffffffu, da, 1);
                    da += __shfl_xor_sync(0xffffffffu, da, 2);
                    vm = (fmaf(mcmt, vm, mnum) + na) * rcpf(mden + da);
                }
                if (mh == 0) smv[mpost] = fmaf(vm, mow, mob);
                barn(2, 128);
                if (it2 < OUTL) {
                    float acc = sdb[it2];
#pragma unroll
                    for (int m = 0; m < MOTORN; m++)
                        acc = fmaf(smv[m], sdw[m * OUTL + it2], acc);
                    out[(b * NT + s) * OUTL + it2] = acc;
                }
            } else {
                if (s + 1 < NT && t < SENS)
                    sx[t] = fmaf(inputs[(b * NT + s + 1) * SENS + t],
                                 input_w[t], input_b[t]);
            }
            __syncthreads();   // step end
        }
    } else {
        // ================= DENSE FALLBACK (any wiring) =================
        const int j = t;
        float cmt = 0.f, gl = 0.f, gv = 0.f;
        if (j < UNITS) {
            cmt = cm[j] * (float)UNF; gl = gleak[j]; gv = gl * vleak[j];
            vsh0[j] = 0.f;
        }
        __syncthreads();
        float* cur = vsh0; float* nxt = vsh1;
        for (int s = 0; s < NT; s++) {
            if (t < SENS)
                sx[t] = fmaf(inputs[(b * NT + s) * SENS + t], input_w[t], input_b[t]);
            __syncthreads();
            float sn = 0.f, sd = 0.f;
            if (j < UNITS) {
                for (int i = 0; i < SENS; i++) {
                    float m = smask[i * UNITS + j];
                    if (m != 0.f) {
                        float sg = ssig[i * UNITS + j];
                        float e = ex2f(LOG2E * sg * (smu[i * UNITS + j] - sx[i]));
                        float sv = rcpf(1.f + e);
                        float wm = swt[i * UNITS + j] * m;
                        sd += wm * sv;
                        sn += wm * serev[i * UNITS + j] * sv;
                    }
                }
            }
            for (int u = 0; u < UNF; u++) {
                float na = sn, da = sd;
                if (j < UNITS) {
                    for (int i = 0; i < UNITS; i++) {
                        float m = mask[i * UNITS + j];
                        if (m != 0.f) {
                            float sg = sig[i * UNITS + j];
                            float e = ex2f(LOG2E * sg * (mu[i * UNITS + j] - cur[i]));
                            float sv = rcpf(1.f + e);
                            float wm = wt[i * UNITS + j] * m;
                            da += wm * sv;
                            na += wm * erev[i * UNITS + j] * sv;
                        }
                    }
                    nxt[j] = (fmaf(cmt, cur[j], gv) + na) * rcpf(cmt + gl + da + EPSF);
                }
                __syncthreads();
                float* tmp = cur; cur = nxt; nxt = tmp;
            }
            if (t < OUTL) {
                float acc = sdb[t];
                for (int m = 0; m < MOTORN; m++)
                    acc = fmaf(fmaf(cur[m], output_w[m], output_b[m]),
                               sdw[m * OUTL + t], acc);
                out[(b * NT + s) * OUTL + t] = acc;
            }
            __syncthreads();
        }
    }
}

extern "C" void kernel_launch(void* const* d_in, const int* in_sizes, int n_in,
                              void* d_out, int out_size)
{
    const float* inputs   = (const float*)d_in[0];
    const float* input_w  = (const float*)d_in[1];
    const float* input_b  = (const float*)d_in[2];
    const float* smu      = (const float*)d_in[3];
    const float* ssig     = (const float*)d_in[4];
    const float* swt      = (const float*)d_in[5];
    const float* serev    = (const float*)d_in[6];
    const float* smask    = (const float*)d_in[7];
    const float* mu       = (const float*)d_in[8];
    const float* sig      = (const float*)d_in[9];
    const float* wt       = (const float*)d_in[10];
    const float* erev     = (const float*)d_in[11];
    const float* mask     = (const float*)d_in[12];
    const float* gleak    = (const float*)d_in[13];
    const float* vleak    = (const float*)d_in[14];
    const float* cm       = (const float*)d_in[15];
    const float* output_w = (const float*)d_in[16];
    const float* output_b = (const float*)d_in[17];
    const float* dense_w  = (const float*)d_in[18];
    const float* dense_b  = (const float*)d_in[19];
    float* out = (float*)d_out;

    prep_kernel<<<UNITS, 32>>>(smu, ssig, swt, serev, smask, mu, sig, wt, erev, mask);
    ncp_kernel<<<NB, NTHREADS>>>(inputs, input_w, input_b,
                                 smu, ssig, swt, serev, smask,
                                 mu, sig, wt, erev, mask,
                                 gleak, vleak, cm,
                                 output_w, output_b, dense_w, dense_b, out);
}

// round 4
// speedup vs baseline: 1.0132x; 1.0132x over previous
#include <cuda_runtime.h>

#define UNITS  224
#define SENS   64
#define MOTORN 32
#define CMDN   64
#define INTERN 128
#define OUTL   32
#define NB     32
#define NT     32
#define UNF    6
#define CAPS   32    // sensory synapses per post
#define CAPI   64    // cmd post: inter presynapses
#define CAPC   16    // cmd post: cmd presynapses (sequential core)
#define CAPM   32    // motor post: presynapses
#define LOG2E  1.4426950408889634f
#define EPSF   1e-8f

// ---------------- compacted tables (prep) ----------------
__device__ float4 g_ssyn[UNITS * CAPS];  // {sig*log2e, sig*mu*log2e, wm, wm*erev}
__device__ int    g_sidx[UNITS * CAPS];
__device__ int    g_scnt[UNITS];
__device__ float4 g_cisyn[CMDN * CAPI];  // cmd <- inter
__device__ int    g_ciix [CMDN * CAPI];  // inter-local 0..127
__device__ int    g_cic  [CMDN];
__device__ float4 g_ccsyn[CMDN * CAPC];  // cmd <- cmd (sequential)
__device__ int    g_ccix [CMDN * CAPC];  // cmd-local 0..63
__device__ int    g_ccc  [CMDN];
__device__ float4 g_msyn [MOTORN * CAPM]; // motor <- (cmd|inter)
__device__ int    g_mtix [MOTORN * CAPM]; // pre-32 in [0,192)
__device__ int    g_mc   [MOTORN];
__device__ int    g_bad;

// ---------------- scratch ----------------
__device__ float  g_vtraj[NB * NT * UNF * INTERN]; // inter v entering unfold u
__device__ float2 g_ssum [NB * NT * 96];           // sensory (num,den), posts 0..95
__device__ float2 g_pcmd [NB * NT * UNF * CMDN];   // cmd partial (na,da) from inter
__device__ float  g_ctraj[NB * NT * UNF * CMDN];   // cmd v entering unfold u
__device__ float2 g_mac  [NB * NT * UNF * MOTORN]; // motor affine (a,c)
__device__ float  g_mv   [NB * NT * MOTORN];       // motor v*ow+ob

__device__ __forceinline__ float ex2f(float x) {
    float r; asm("ex2.approx.ftz.f32 %0, %1;" : "=f"(r) : "f"(x)); return r;
}
__device__ __forceinline__ float rcpf(float x) {
    float r; asm("rcp.approx.ftz.f32 %0, %1;" : "=f"(r) : "f"(x)); return r;
}

__global__ void k0_init() { g_bad = 0; }

// one warp per post column
__global__ void prep_kernel(
    const float* __restrict__ smu,  const float* __restrict__ ssig,
    const float* __restrict__ swt,  const float* __restrict__ serev,
    const float* __restrict__ smask,
    const float* __restrict__ mu,   const float* __restrict__ sig,
    const float* __restrict__ wt,   const float* __restrict__ erev,
    const float* __restrict__ mask)
{
    const int j = blockIdx.x;
    const int lane = threadIdx.x;
    const unsigned FULL = 0xffffffffu;
    const unsigned lt = (1u << lane) - 1u;
    int bad = 0;

    if (j < MOTORN) {
        int cnt = 0;
        for (int i0 = 0; i0 < UNITS; i0 += 32) {
            int i = i0 + lane, gi = i * UNITS + j;
            float m = mask[gi];
            bool act = (m != 0.f);
            if (act && i < MOTORN) bad = 1;
            unsigned bal = __ballot_sync(FULL, act);
            if (act) {
                int pos = cnt + __popc(bal & lt);
                if (pos < CAPM && i >= MOTORN) {
                    float sg = sig[gi]; float wm = wt[gi] * m;
                    g_msyn[j * CAPM + pos] =
                        make_float4(sg * LOG2E, sg * mu[gi] * LOG2E, wm, wm * erev[gi]);
                    g_mtix[j * CAPM + pos] = i - MOTORN;
                }
            }
            cnt += __popc(bal);
        }
        if (cnt > CAPM) bad = 1;
        if (lane == 0) g_mc[j] = cnt;
    } else if (j < MOTORN + CMDN) {
        const int c = j - MOTORN;
        int icnt = 0, ccnt = 0;
        for (int i0 = 0; i0 < UNITS; i0 += 32) {
            int i = i0 + lane, gi = i * UNITS + j;
            float m = mask[gi];
            bool act = (m != 0.f);
            if (act && i < MOTORN) bad = 1;
            bool isI = act && (i >= MOTORN + CMDN);
            bool isC = act && (i >= MOTORN) && (i < MOTORN + CMDN);
            unsigned balI = __ballot_sync(FULL, isI);
            unsigned balC = __ballot_sync(FULL, isC);
            if (isI) {
                int pos = icnt + __popc(balI & lt);
                if (pos < CAPI) {
                    float sg = sig[gi]; float wm = wt[gi] * m;
                    g_cisyn[c * CAPI + pos] =
                        make_float4(sg * LOG2E, sg * mu[gi] * LOG2E, wm, wm * erev[gi]);
                    g_ciix[c * CAPI + pos] = i - (MOTORN + CMDN);
                }
            }
            if (isC) {
                int pos = ccnt + __popc(balC & lt);
                if (pos < CAPC) {
                    float sg = sig[gi]; float wm = wt[gi] * m;
                    g_ccsyn[c * CAPC + pos] =
                        make_float4(sg * LOG2E, sg * mu[gi] * LOG2E, wm, wm * erev[gi]);
                    g_ccix[c * CAPC + pos] = i - MOTORN;
                }
            }
            icnt += __popc(balI);
            ccnt += __popc(balC);
        }
        if (icnt > CAPI || ccnt > CAPC) bad = 1;
        if (lane == 0) { g_cic[c] = icnt; g_ccc[c] = ccnt; }
    } else {
        // inter post: must receive zero recurrent synapses
        for (int i0 = 0; i0 < UNITS; i0 += 32)
            if (mask[(i0 + lane) * UNITS + j] != 0.f) bad = 1;
    }

    // sensory (all posts)
    int cnt = 0;
    for (int i0 = 0; i0 < SENS; i0 += 32) {
        int i = i0 + lane, gi = i * UNITS + j;
        float m = smask[gi];
        bool act = (m != 0.f);
        unsigned bal = __ballot_sync(FULL, act);
        if (act) {
            int pos = cnt + __popc(bal & lt);
            if (pos < CAPS) {
                float sg = ssig[gi]; float wm = swt[gi] * m;
                g_ssyn[j * CAPS + pos] =
                    make_float4(sg * LOG2E, sg * smu[gi] * LOG2E, wm, wm * serev[gi]);
                g_sidx[j * CAPS + pos] = i;
            }
        }
        cnt += __popc(bal);
    }
    if (cnt > CAPS) bad = 1;
    if (lane == 0) g_scnt[j] = cnt;

    bad = (__ballot_sync(FULL, bad) != 0u);
    if (lane == 0 && bad) atomicOr(&g_bad, 1);
}

// K2: sensory sums for posts<96 + inter trajectories. grid NB, 224 threads.
__global__ void __launch_bounds__(UNITS)
k2_sens_inter(const float* __restrict__ inputs,
              const float* __restrict__ input_w, const float* __restrict__ input_b,
              const float* __restrict__ gleak, const float* __restrict__ vleak,
              const float* __restrict__ cm)
{
    if (g_bad) return;
    __shared__ float sx[2][SENS];
    const int b = blockIdx.x;
    const int j = threadIdx.x;
    const float iw = (j < SENS) ? input_w[j] : 0.f;
    const float ib = (j < SENS) ? input_b[j] : 0.f;
    const int scnt = g_scnt[j];
    const float cmt = cm[j] * (float)UNF;
    const float gl  = gleak[j];
    const float gv  = gl * vleak[j];
    float v = 0.f;

    for (int s = 0; s < NT; s++) {
        float* xb = sx[s & 1];
        if (j < SENS)
            xb[j] = fmaf(inputs[(b * NT + s) * SENS + j], iw, ib);
        __syncthreads();
        float sn = 0.f, sd = 0.f;
#pragma unroll 4
        for (int k = 0; k < scnt; k++) {
            float4 sy = g_ssyn[j * CAPS + k];
            float x = xb[g_sidx[j * CAPS + k]];
            float sg = rcpf(1.f + ex2f(fmaf(-sy.x, x, sy.y)));
            sd = fmaf(sy.z, sg, sd); sn = fmaf(sy.w, sg, sn);
        }
        if (j < MOTORN + CMDN) {
            g_ssum[(b * NT + s) * 96 + j] = make_float2(sn, sd);
        } else {
            const int ii = j - (MOTORN + CMDN);
            const float num  = gv + sn;
            const float dinv = rcpf(cmt + gl + sd + EPSF);
            int base = ((b * NT + s) * UNF) * INTERN + ii;
#pragma unroll
            for (int u = 0; u < UNF; u++) {
                g_vtraj[base + u * INTERN] = v;
                v = fmaf(cmt, v, num) * dinv;
            }
        }
    }
}

// K2.5: cmd partial sums over inter pres. grid NB*NT*UNF, 256 threads.
__global__ void __launch_bounds__(256)
k25_cmdpart()
{
    if (g_bad) return;
    __shared__ float vrow[INTERN];
    const int blk = blockIdx.x;
    const int t = threadIdx.x;
    if (t < INTERN) vrow[t] = g_vtraj[blk * INTERN + t];
    __syncthreads();
    const int c = t >> 2, h = t & 3;
    const int cnt = g_cic[c];
    float na = 0.f, da = 0.f;
#pragma unroll 4
    for (int k = h; k < cnt; k += 4) {
        float4 sy = g_cisyn[c * CAPI + k];
        float vp = vrow[g_ciix[c * CAPI + k]];
        float sg = rcpf(1.f + ex2f(fmaf(-sy.x, vp, sy.y)));
        da = fmaf(sy.z, sg, da); na = fmaf(sy.w, sg, na);
    }
    na += __shfl_xor_sync(0xffffffffu, na, 1);
    na += __shfl_xor_sync(0xffffffffu, na, 2);
    da += __shfl_xor_sync(0xffffffffu, da, 1);
    da += __shfl_xor_sync(0xffffffffu, da, 2);
    if (h == 0) g_pcmd[blk * CMDN + c] = make_float2(na, da);
}

// K3: the sequential core. grid NB, 32 threads (2 cmd posts per thread).
__global__ void __launch_bounds__(32)
k3_cmdseq(const float* __restrict__ gleak, const float* __restrict__ vleak,
          const float* __restrict__ cm)
{
    if (g_bad) return;
    __shared__ __align__(8) float vrow[CMDN];
    const int b = blockIdx.x;
    const int t = threadIdx.x;
    const int p0 = 2 * t, p1 = 2 * t + 1;
    const int j0 = MOTORN + p0, j1 = MOTORN + p1;
    const float cmt0 = cm[j0] * (float)UNF, cmt1 = cm[j1] * (float)UNF;
    const float gl0 = gleak[j0], gl1 = gleak[j1];
    const float gv0 = gl0 * vleak[j0], gv1 = gl1 * vleak[j1];
    const int cc0 = g_ccc[p0], cc1 = g_ccc[p1];
    float v0 = 0.f, v1 = 0.f;

    float2 ss0 = g_ssum[(b * NT) * 96 + j0];
    float2 ss1 = g_ssum[(b * NT) * 96 + j1];
    float2 pc0 = g_pcmd[(b * NT * UNF) * CMDN + p0];
    float2 pc1 = g_pcmd[(b * NT * UNF) * CMDN + p1];

    for (int s = 0; s < NT; s++) {
        const int sn1 = (s + 1 < NT) ? s + 1 : s;
        float2 nss0 = g_ssum[(b * NT + sn1) * 96 + j0];   // prefetch next step
        float2 nss1 = g_ssum[(b * NT + sn1) * 96 + j1];
        const float cn0 = gv0 + ss0.x, cd0 = cmt0 + gl0 + ss0.y + EPSF;
        const float cn1 = gv1 + ss1.x, cd1 = cmt1 + gl1 + ss1.y + EPSF;
#pragma unroll
        for (int u = 0; u < UNF; u++) {
            // publish current v (smem for peers, global for motors)
            ((float2*)vrow)[t] = make_float2(v0, v1);
            const int row = ((b * NT + s) * UNF + u) * CMDN;
            ((float2*)(g_ctraj + row))[t] = make_float2(v0, v1);
            __syncwarp();
            // prefetch next unfold's partials
            int nu = (u < UNF - 1) ? u + 1 : 0;
            int ns = (u < UNF - 1) ? s : sn1;
            const int nrow = ((b * NT + ns) * UNF + nu) * CMDN;
            float2 npc0 = g_pcmd[nrow + p0];
            float2 npc1 = g_pcmd[nrow + p1];
            float na0 = 0.f, da0 = 0.f, na1 = 0.f, da1 = 0.f;
            for (int k = 0; k < cc0; k++) {
                float4 sy = g_ccsyn[p0 * CAPC + k];
                float vp = vrow[g_ccix[p0 * CAPC + k]];
                float sg = rcpf(1.f + ex2f(fmaf(-sy.x, vp, sy.y)));
                da0 = fmaf(sy.z, sg, da0); na0 = fmaf(sy.w, sg, na0);
            }
            for (int k = 0; k < cc1; k++) {
                float4 sy = g_ccsyn[p1 * CAPC + k];
                float vp = vrow[g_ccix[p1 * CAPC + k]];
                float sg = rcpf(1.f + ex2f(fmaf(-sy.x, vp, sy.y)));
                da1 = fmaf(sy.z, sg, da1); na1 = fmaf(sy.w, sg, na1);
            }
            v0 = (fmaf(cmt0, v0, cn0) + pc0.x + na0) * rcpf(cd0 + pc0.y + da0);
            v1 = (fmaf(cmt1, v1, cn1) + pc1.x + na1) * rcpf(cd1 + pc1.y + da1);
            pc0 = npc0; pc1 = npc1;
            __syncwarp();
        }
        ss0 = nss0; ss1 = nss1;
    }
}

// K4a: motor affine coefficients. grid NB*NT*UNF, 128 threads.
__global__ void __launch_bounds__(128)
k4a_motorpart(const float* __restrict__ gleak, const float* __restrict__ vleak,
              const float* __restrict__ cm)
{
    if (g_bad) return;
    __shared__ float trow[CMDN + INTERN];   // [0,64)=cmd, [64,192)=inter
    const int blk = blockIdx.x;             // (b*NT+s)*UNF+u
    const int bs = blk / UNF;
    const int t = threadIdx.x;
    if (t < CMDN) trow[t] = g_ctraj[blk * CMDN + t];
    trow[CMDN + t] = g_vtraj[blk * INTERN + t];
    __syncthreads();
    const int m = t >> 2, h = t & 3;
    const int cnt = g_mc[m];
    float na = 0.f, da = 0.f;
#pragma unroll 4
    for (int k = h; k < cnt; k += 4) {
        float4 sy = g_msyn[m * CAPM + k];
        float vp = trow[g_mtix[m * CAPM + k]];
        float sg = rcpf(1.f + ex2f(fmaf(-sy.x, vp, sy.y)));
        da = fmaf(sy.z, sg, da); na = fmaf(sy.w, sg, na);
    }
    na += __shfl_xor_sync(0xffffffffu, na, 1);
    na += __shfl_xor_sync(0xffffffffu, na, 2);
    da += __shfl_xor_sync(0xffffffffu, da, 1);
    da += __shfl_xor_sync(0xffffffffu, da, 2);
    if (h == 0) {
        float2 ssm = g_ssum[bs * 96 + m];
        float cmt = cm[m] * (float)UNF;
        float gl = gleak[m];
        float dinv = rcpf(cmt + gl + ssm.y + da + EPSF);
        float a = cmt * dinv;
        float c = (fmaf(gl, vleak[m], ssm.x) + na) * dinv;
        g_mac[blk * MOTORN + m] = make_float2(a, c);
    }
}

// K4b: motor affine scan. grid 4, 256 threads: thread = (b, m).
__global__ void __launch_bounds__(256)
k4b_motorscan(const float* __restrict__ output_w, const float* __restrict__ output_b)
{
    if (g_bad) return;
    const int g = blockIdx.x * 256 + threadIdx.x;
    const int b = g >> 5, m = g & 31;
    const float ow = output_w[m], ob = output_b[m];
    float v = 0.f;
    for (int s = 0; s < NT; s++) {
#pragma unroll
        for (int u = 0; u < UNF; u++) {
            float2 ac = g_mac[(((b * NT + s) * UNF) + u) * MOTORN + m];
            v = fmaf(ac.x, v, ac.y);
        }
        g_mv[(b * NT + s) * MOTORN + m] = fmaf(v, ow, ob);
    }
}

// K4c: output GEMV. grid NB*NT, 32 threads.
__global__ void __launch_bounds__(32)
k4c_output(const float* __restrict__ dense_w, const float* __restrict__ dense_b,
           float* __restrict__ out)
{
    if (g_bad) return;
    __shared__ float ym[MOTORN];
    const int bs = blockIdx.x;
    const int o = threadIdx.x;
    ym[o] = g_mv[bs * MOTORN + o];
    __syncwarp();
    float acc = dense_b[o];
#pragma unroll
    for (int m = 0; m < MOTORN; m++)
        acc = fmaf(ym[m], dense_w[m * OUTL + o], acc);
    out[bs * OUTL + o] = acc;
}

// Dense fallback (any wiring). Runs only if g_bad.
__global__ void __launch_bounds__(UNITS)
kfall_dense(
    const float* __restrict__ inputs,
    const float* __restrict__ input_w, const float* __restrict__ input_b,
    const float* __restrict__ smu,  const float* __restrict__ ssig,
    const float* __restrict__ swt,  const float* __restrict__ serev,
    const float* __restrict__ smask,
    const float* __restrict__ mu,   const float* __restrict__ sig,
    const float* __restrict__ wt,   const float* __restrict__ erev,
    const float* __restrict__ mask,
    const float* __restrict__ gleak, const float* __restrict__ vleak,
    const float* __restrict__ cm,
    const float* __restrict__ output_w, const float* __restrict__ output_b,
    const float* __restrict__ dense_w,  const float* __restrict__ dense_b,
    float* __restrict__ out)
{
    if (!g_bad) return;
    __shared__ float v0s[UNITS], v1s[UNITS], sx[SENS];
    const int b = blockIdx.x;
    const int j = threadIdx.x;
    float cmt = cm[j] * (float)UNF, gl = gleak[j], gv = gl * vleak[j];
    v0s[j] = 0.f;
    __syncthreads();
    float* cur = v0s; float* nxt = v1s;
    for (int s = 0; s < NT; s++) {
        if (j < SENS)
            sx[j] = fmaf(inputs[(b * NT + s) * SENS + j], input_w[j], input_b[j]);
        __syncthreads();
        float sn = 0.f, sd = 0.f;
        for (int i = 0; i < SENS; i++) {
            float m = smask[i * UNITS + j];
            if (m != 0.f) {
                float sg = ssig[i * UNITS + j];
                float sv = rcpf(1.f + ex2f(LOG2E * sg * (smu[i * UNITS + j] - sx[i])));
                float wm = swt[i * UNITS + j] * m;
                sd += wm * sv; sn += wm * serev[i * UNITS + j] * sv;
            }
        }
        for (int u = 0; u < UNF; u++) {
            float na = sn, da = sd;
            for (int i = 0; i < UNITS; i++) {
                float m = mask[i * UNITS + j];
                if (m != 0.f) {
                    float sg = sig[i * UNITS + j];
                    float sv = rcpf(1.f + ex2f(LOG2E * sg * (mu[i * UNITS + j] - cur[i])));
                    float wm = wt[i * UNITS + j] * m;
                    da += wm * sv; na += wm * erev[i * UNITS + j] * sv;
                }
            }
            nxt[j] = (fmaf(cmt, cur[j], gv) + na) * rcpf(cmt + gl + da + EPSF);
            __syncthreads();
            float* tmp = cur; cur = nxt; nxt = tmp;
        }
        if (j < OUTL) {
            float acc = dense_b[j];
            for (int m = 0; m < MOTORN; m++)
                acc = fmaf(fmaf(cur[m], output_w[m], output_b[m]),
                           dense_w[m * OUTL + j], acc);
            out[(b * NT + s) * OUTL + j] = acc;
        }
        __syncthreads();
    }
}

extern "C" void kernel_launch(void* const* d_in, const int* in_sizes, int n_in,
                              void* d_out, int out_size)
{
    const float* inputs   = (const float*)d_in[0];
    const float* input_w  = (const float*)d_in[1];
    const float* input_b  = (const float*)d_in[2];
    const float* smu      = (const float*)d_in[3];
    const float* ssig     = (const float*)d_in[4];
    const float* swt      = (const float*)d_in[5];
    const float* serev    = (const float*)d_in[6];
    const float* smask    = (const float*)d_in[7];
    const float* mu       = (const float*)d_in[8];
    const float* sig      = (const float*)d_in[9];
    const float* wt       = (const float*)d_in[10];
    const float* erev     = (const float*)d_in[11];
    const float* mask     = (const float*)d_in[12];
    const float* gleak    = (const float*)d_in[13];
    const float* vleak    = (const float*)d_in[14];
    const float* cm       = (const float*)d_in[15];
    const float* output_w = (const float*)d_in[16];
    const float* output_b = (const float*)d_in[17];
    const float* dense_w  = (const float*)d_in[18];
    const float* dense_b  = (const float*)d_in[19];
    float* out = (float*)d_out;

    k0_init<<<1, 1>>>();
    prep_kernel<<<UNITS, 32>>>(smu, ssig, swt, serev, smask, mu, sig, wt, erev, mask);
    k2_sens_inter<<<NB, UNITS>>>(inputs, input_w, input_b, gleak, vleak, cm);
    k25_cmdpart<<<NB * NT * UNF, 256>>>();
    k3_cmdseq<<<NB, 32>>>(gleak, vleak, cm);
    k4a_motorpart<<<NB * NT * UNF, 128>>>(gleak, vleak, cm);
    k4b_motorscan<<<4, 256>>>(output_w, output_b);
    k4c_output<<<NB * NT, 32>>>(dense_w, dense_b, out);
    kfall_dense<<<NB, UNITS>>>(inputs, input_w, input_b,
                               smu, ssig, swt, serev, smask,
                               mu, sig, wt, erev, mask,
                               gleak, vleak, cm,
                               output_w, output_b, dense_w, dense_b, out);
}

// round 5
// speedup vs baseline: 1.0723x; 1.0583x over previous
#include <cuda_runtime.h>

#define UNITS  224
#define SENS   64
#define MOTORN 32
#define CMDN   64
#define INTERN 128
#define OUTL   32
#define NB     32
#define NT     32
#define UNF    6
#define CAPS   32
#define CAPI   64
#define CAPC   16
#define CAPM   32
#define NBLK   148
#define NTH    256
#define LOG2E  1.4426950408889634f
#define EPSF   1e-8f

// ---------------- compacted tables ----------------
__device__ float4 g_ssyn [UNITS * CAPS];   // {sig*log2e, sig*mu*log2e, wm, wm*erev}
__device__ int    g_sidx [UNITS * CAPS];
__device__ int    g_scnt [UNITS];
__device__ float4 g_cisyn[CMDN * CAPI];    // cmd <- inter
__device__ int    g_ciix [CMDN * CAPI];    // inter-local 0..127
__device__ int    g_cic  [CMDN];
__device__ float4 g_ccsyn[CMDN * CAPC];    // cmd <- cmd
__device__ int    g_ccix [CMDN * CAPC];    // cmd-local 0..63
__device__ int    g_ccc  [CMDN];
__device__ float4 g_msyn [MOTORN * CAPM];  // motor <- (cmd|inter)
__device__ int    g_mtix [MOTORN * CAPM];  // pre-32: cmd 0..63, inter 64..191
__device__ int    g_mc   [MOTORN];
__device__ int    g_badv [UNITS];

// ---------------- scratch ----------------
__device__ float2 g_ssum [NB * NT * 96];
__device__ float2 g_iac  [NB * NT * INTERN];
__device__ float  g_vtraj[NB * NT * UNF * INTERN];
__device__ float2 g_pcmd [NB * NT * UNF * CMDN];
__device__ float  g_ctraj[NB * NT * UNF * CMDN];
__device__ float2 g_mac  [NB * NT * UNF * MOTORN];

// monotonic grid barrier counter (never reset; zero-init at module load)
__device__ unsigned g_arrive;

__device__ __forceinline__ float ex2f(float x) {
    float r; asm("ex2.approx.ftz.f32 %0, %1;" : "=f"(r) : "f"(x)); return r;
}
__device__ __forceinline__ float rcpf(float x) {
    float r; asm("rcp.approx.ftz.f32 %0, %1;" : "=f"(r) : "f"(x)); return r;
}

__device__ __forceinline__ void grid_barrier() {
    __syncthreads();
    if (threadIdx.x == 0) {
        __threadfence();
        unsigned old = atomicAdd(&g_arrive, 1u);
        unsigned target = (old / NBLK + 1u) * NBLK;
        while (atomicAdd(&g_arrive, 0u) < target) { __nanosleep(64); }
        __threadfence();
    }
    __syncthreads();
}

__global__ void __launch_bounds__(NTH, 1)
ncp_persistent(
    const float* __restrict__ inputs,
    const float* __restrict__ input_w, const float* __restrict__ input_b,
    const float* __restrict__ smu,  const float* __restrict__ ssig,
    const float* __restrict__ swt,  const float* __restrict__ serev,
    const float* __restrict__ smask,
    const float* __restrict__ mu,   const float* __restrict__ sig,
    const float* __restrict__ wt,   const float* __restrict__ erev,
    const float* __restrict__ mask,
    const float* __restrict__ gleak, const float* __restrict__ vleak,
    const float* __restrict__ cm,
    const float* __restrict__ output_w, const float* __restrict__ output_b,
    const float* __restrict__ dense_w,  const float* __restrict__ dense_b,
    float* __restrict__ out)
{
    __shared__ float sx[SENS];
    __shared__ float vr[UNF * INTERN];          // P2: inter rows
    __shared__ float trow[UNF * 192];           // P4: cmd+inter rows
    __shared__ float vrow[CMDN];                // P3
    __shared__ float ym[MOTORN];                // P5
    __shared__ float sdw[MOTORN * OUTL];        // P5 / fallback
    __shared__ float fb0[UNITS], fb1[UNITS];    // fallback

    const int t   = threadIdx.x;
    const int bx  = blockIdx.x;
    const int wid = t >> 5;
    const int lane = t & 31;

    // ================= P0: prep (one warp per post column) =================
    {
        const unsigned FULL = 0xffffffffu;
        const unsigned lt = (1u << lane) - 1u;
        const int j = bx * 8 + wid;
        if (j < UNITS) {
            int bad = 0;
            if (j < MOTORN) {
                int cnt = 0;
                for (int i0 = 0; i0 < UNITS; i0 += 32) {
                    int i = i0 + lane, gi = i * UNITS + j;
                    float m = mask[gi];
                    bool act = (m != 0.f);
                    if (act && i < MOTORN) bad = 1;
                    unsigned bal = __ballot_sync(FULL, act);
                    if (act) {
                        int pos = cnt + __popc(bal & lt);
                        if (pos < CAPM && i >= MOTORN) {
                            float sg = sig[gi]; float wm = wt[gi] * m;
                            g_msyn[j * CAPM + pos] =
                                make_float4(sg * LOG2E, sg * mu[gi] * LOG2E, wm, wm * erev[gi]);
                            g_mtix[j * CAPM + pos] = i - MOTORN;
                        }
                    }
                    cnt += __popc(bal);
                }
                if (cnt > CAPM) bad = 1;
                if (lane == 0) g_mc[j] = cnt;
            } else if (j < MOTORN + CMDN) {
                const int c = j - MOTORN;
                int icnt = 0, ccnt = 0;
                for (int i0 = 0; i0 < UNITS; i0 += 32) {
                    int i = i0 + lane, gi = i * UNITS + j;
                    float m = mask[gi];
                    bool act = (m != 0.f);
                    if (act && i < MOTORN) bad = 1;
                    bool isI = act && (i >= MOTORN + CMDN);
                    bool isC = act && (i >= MOTORN) && (i < MOTORN + CMDN);
                    unsigned balI = __ballot_sync(FULL, isI);
                    unsigned balC = __ballot_sync(FULL, isC);
                    if (isI) {
                        int pos = icnt + __popc(balI & lt);
                        if (pos < CAPI) {
                            float sg = sig[gi]; float wm = wt[gi] * m;
                            g_cisyn[c * CAPI + pos] =
                                make_float4(sg * LOG2E, sg * mu[gi] * LOG2E, wm, wm * erev[gi]);
                            g_ciix[c * CAPI + pos] = i - (MOTORN + CMDN);
                        }
                    }
                    if (isC) {
                        int pos = ccnt + __popc(balC & lt);
                        if (pos < CAPC) {
                            float sg = sig[gi]; float wm = wt[gi] * m;
                            g_ccsyn[c * CAPC + pos] =
                                make_float4(sg * LOG2E, sg * mu[gi] * LOG2E, wm, wm * erev[gi]);
                            g_ccix[c * CAPC + pos] = i - MOTORN;
                        }
                    }
                    icnt += __popc(balI);
                    ccnt += __popc(balC);
                }
                if (icnt > CAPI || ccnt > CAPC) bad = 1;
                if (lane == 0) { g_cic[c] = icnt; g_ccc[c] = ccnt; }
            } else {
                for (int i0 = 0; i0 < UNITS; i0 += 32)
                    if (mask[(i0 + lane) * UNITS + j] != 0.f) bad = 1;
            }
            // sensory
            int cnt = 0;
            for (int i0 = 0; i0 < SENS; i0 += 32) {
                int i = i0 + lane, gi = i * UNITS + j;
                float m = smask[gi];
                bool act = (m != 0.f);
                unsigned bal = __ballot_sync(FULL, act);
                if (act) {
                    int pos = cnt + __popc(bal & lt);
                    if (pos < CAPS) {
                        float sg = ssig[gi]; float wm = swt[gi] * m;
                        g_ssyn[j * CAPS + pos] =
                            make_float4(sg * LOG2E, sg * smu[gi] * LOG2E, wm, wm * serev[gi]);
                        g_sidx[j * CAPS + pos] = i;
                    }
                }
                cnt += __popc(bal);
            }
            if (cnt > CAPS) bad = 1;
            if (lane == 0) g_scnt[j] = cnt;
            bad = (__ballot_sync(FULL, bad) != 0u);
            if (lane == 0) g_badv[j] = bad;
        }
    }
    grid_barrier();   // #1

    const int anybad = __syncthreads_or((t < UNITS) ? g_badv[t] : 0);

    if (anybad) {
        // ============== DENSE FALLBACK (blocks 0..31, any wiring) ==============
        if (bx < NB) {
            const int b = bx, j = t;
            float cmt = 0.f, gl = 0.f, gv = 0.f;
            if (j < UNITS) {
                cmt = cm[j] * (float)UNF; gl = gleak[j]; gv = gl * vleak[j];
                fb0[j] = 0.f;
            }
            for (int i = t; i < MOTORN * OUTL; i += NTH) sdw[i] = dense_w[i];
            __syncthreads();
            float* cur = fb0; float* nxt = fb1;
            for (int s = 0; s < NT; s++) {
                if (t < SENS)
                    sx[t] = fmaf(inputs[(b * NT + s) * SENS + t], input_w[t], input_b[t]);
                __syncthreads();
                float sn = 0.f, sd = 0.f;
                if (j < UNITS) {
                    for (int i = 0; i < SENS; i++) {
                        float m = smask[i * UNITS + j];
                        if (m != 0.f) {
                            float sg = ssig[i * UNITS + j];
                            float sv = rcpf(1.f + ex2f(LOG2E * sg * (smu[i * UNITS + j] - sx[i])));
                            float wm = swt[i * UNITS + j] * m;
                            sd += wm * sv; sn += wm * serev[i * UNITS + j] * sv;
                        }
                    }
                }
                for (int u = 0; u < UNF; u++) {
                    float na = sn, da = sd;
                    if (j < UNITS) {
                        for (int i = 0; i < UNITS; i++) {
                            float m = mask[i * UNITS + j];
                            if (m != 0.f) {
                                float sg = sig[i * UNITS + j];
                                float sv = rcpf(1.f + ex2f(LOG2E * sg * (mu[i * UNITS + j] - cur[i])));
                                float wm = wt[i * UNITS + j] * m;
                                da += wm * sv; na += wm * erev[i * UNITS + j] * sv;
                            }
                        }
                        nxt[j] = (fmaf(cmt, cur[j], gv) + na) * rcpf(cmt + gl + da + EPSF);
                    }
                    __syncthreads();
                    float* tmp = cur; cur = nxt; nxt = tmp;
                }
                if (t < OUTL) {
                    float acc = dense_b[t];
                    for (int m = 0; m < MOTORN; m++)
                        acc = fmaf(fmaf(cur[m], output_w[m], output_b[m]),
                                   sdw[m * OUTL + t], acc);
                    out[(b * NT + s) * OUTL + t] = acc;
                }
                __syncthreads();
            }
        }
        return;   // all blocks exit; equal barrier counts everywhere
    }

    // ================= P1: sensory sums + inter affine coeffs =================
    for (int it = bx; it < NB * NT; it += NBLK) {
        if (t < SENS)
            sx[t] = fmaf(inputs[it * SENS + t], input_w[t], input_b[t]);
        __syncthreads();
        if (t < UNITS) {
            const int scnt = g_scnt[t];
            float sn = 0.f, sd = 0.f;
#pragma unroll 4
            for (int k = 0; k < scnt; k++) {
                float4 sy = g_ssyn[t * CAPS + k];
                float x = sx[g_sidx[t * CAPS + k]];
                float sg = rcpf(1.f + ex2f(fmaf(-sy.x, x, sy.y)));
                sd = fmaf(sy.z, sg, sd); sn = fmaf(sy.w, sg, sn);
            }
            if (t < MOTORN + CMDN) {
                g_ssum[it * 96 + t] = make_float2(sn, sd);
            } else {
                float cmt = cm[t] * (float)UNF;
                float gl = gleak[t];
                float dinv = rcpf(cmt + gl + sd + EPSF);
                g_iac[it * INTERN + (t - 96)] =
                    make_float2(cmt * dinv, fmaf(gl, vleak[t], sn) * dinv);
            }
        }
        __syncthreads();
    }
    grid_barrier();   // #2

    // ================= P1.5: inter affine scans =================
    {
        const int g = bx * NTH + t;
        if (g < NB * INTERN) {
            const int b = g >> 7, i = g & 127;
            float v = 0.f;
            for (int s = 0; s < NT; s++) {
                float2 ac = g_iac[(b * NT + s) * INTERN + i];
#pragma unroll
                for (int u = 0; u < UNF; u++) {
                    g_vtraj[((b * NT + s) * UNF + u) * INTERN + i] = v;
                    v = fmaf(ac.x, v, ac.y);
                }
            }
        }
    }
    grid_barrier();   // #3

    // ================= P2: cmd <- inter partial sums =================
    {
        const int c = t >> 2, h = t & 3;
        const int cnt = g_cic[c];
        for (int it = bx; it < NB * NT; it += NBLK) {
            for (int idx = t; idx < UNF * INTERN; idx += NTH)
                vr[idx] = g_vtraj[it * (UNF * INTERN) + idx];
            __syncthreads();
#pragma unroll
            for (int u = 0; u < UNF; u++) {
                const float* __restrict__ vrw = &vr[u * INTERN];
                float na = 0.f, da = 0.f;
#pragma unroll 4
                for (int k = h; k < cnt; k += 4) {
                    float4 sy = g_cisyn[c * CAPI + k];
                    float vp = vrw[g_ciix[c * CAPI + k]];
                    float sg = rcpf(1.f + ex2f(fmaf(-sy.x, vp, sy.y)));
                    da = fmaf(sy.z, sg, da); na = fmaf(sy.w, sg, na);
                }
                na += __shfl_xor_sync(0xffffffffu, na, 1);
                na += __shfl_xor_sync(0xffffffffu, na, 2);
                da += __shfl_xor_sync(0xffffffffu, da, 1);
                da += __shfl_xor_sync(0xffffffffu, da, 2);
                if (h == 0) g_pcmd[(it * UNF + u) * CMDN + c] = make_float2(na, da);
            }
            __syncthreads();
        }
    }
    grid_barrier();   // #4

    // ================= P3: sequential cmd scan (blocks 0..31, warp 0) =========
    if (bx < NB && t < 32) {
        const int b = bx;
        const int p0 = 2 * t, p1 = 2 * t + 1;
        const int j0 = MOTORN + p0, j1 = MOTORN + p1;
        const float cmt0 = cm[j0] * (float)UNF, cmt1 = cm[j1] * (float)UNF;
        const float gl0 = gleak[j0], gl1 = gleak[j1];
        const float gv0 = gl0 * vleak[j0], gv1 = gl1 * vleak[j1];
        const int cc0 = g_ccc[p0], cc1 = g_ccc[p1];
        float v0 = 0.f, v1 = 0.f;

        float2 ss0 = g_ssum[(b * NT) * 96 + j0];
        float2 ss1 = g_ssum[(b * NT) * 96 + j1];
        float2 pc0 = g_pcmd[(b * NT * UNF) * CMDN + p0];
        float2 pc1 = g_pcmd[(b * NT * UNF) * CMDN + p1];

        for (int s = 0; s < NT; s++) {
            const int sn1 = (s + 1 < NT) ? s + 1 : s;
            float2 nss0 = g_ssum[(b * NT + sn1) * 96 + j0];
            float2 nss1 = g_ssum[(b * NT + sn1) * 96 + j1];
            const float cn0 = gv0 + ss0.x, cd0 = cmt0 + gl0 + ss0.y + EPSF;
            const float cn1 = gv1 + ss1.x, cd1 = cmt1 + gl1 + ss1.y + EPSF;
#pragma unroll
            for (int u = 0; u < UNF; u++) {
                ((float2*)vrow)[t] = make_float2(v0, v1);
                const int row = ((b * NT + s) * UNF + u) * CMDN;
                ((float2*)(g_ctraj + row))[t] = make_float2(v0, v1);
                __syncwarp();
                int nu = (u < UNF - 1) ? u + 1 : 0;
                int ns = (u < UNF - 1) ? s : sn1;
                const int nrow = ((b * NT + ns) * UNF + nu) * CMDN;
                float2 npc0 = g_pcmd[nrow + p0];
                float2 npc1 = g_pcmd[nrow + p1];
                float na0 = 0.f, da0 = 0.f, na1 = 0.f, da1 = 0.f;
                for (int k = 0; k < cc0; k++) {
                    float4 sy = g_ccsyn[p0 * CAPC + k];
                    float vp = vrow[g_ccix[p0 * CAPC + k]];
                    float sg = rcpf(1.f + ex2f(fmaf(-sy.x, vp, sy.y)));
                    da0 = fmaf(sy.z, sg, da0); na0 = fmaf(sy.w, sg, na0);
                }
                for (int k = 0; k < cc1; k++) {
                    float4 sy = g_ccsyn[p1 * CAPC + k];
                    float vp = vrow[g_ccix[p1 * CAPC + k]];
                    float sg = rcpf(1.f + ex2f(fmaf(-sy.x, vp, sy.y)));
                    da1 = fmaf(sy.z, sg, da1); na1 = fmaf(sy.w, sg, na1);
                }
                v0 = (fmaf(cmt0, v0, cn0) + pc0.x + na0) * rcpf(cd0 + pc0.y + da0);
                v1 = (fmaf(cmt1, v1, cn1) + pc1.x + na1) * rcpf(cd1 + pc1.y + da1);
                pc0 = npc0; pc1 = npc1;
                __syncwarp();
            }
            ss0 = nss0; ss1 = nss1;
        }
    }
    grid_barrier();   // #5

    // ================= P4: motor partials + affine coeffs =================
    {
        const int m = t >> 3, h = t & 7;
        const int cnt = g_mc[m];
        const float cmt = cm[m] * (float)UNF;
        const float gl = gleak[m];
        const float vl = vleak[m];
        for (int it = bx; it < NB * NT; it += NBLK) {
            for (int idx = t; idx < UNF * CMDN; idx += NTH) {
                int u = idx >> 6, c = idx & 63;
                trow[u * 192 + c] = g_ctraj[(it * UNF + u) * CMDN + c];
            }
            for (int idx = t; idx < UNF * INTERN; idx += NTH) {
                int u = idx >> 7, i = idx & 127;
                trow[u * 192 + CMDN + i] = g_vtraj[it * (UNF * INTERN) + idx];
            }
            __syncthreads();
#pragma unroll
            for (int u = 0; u < UNF; u++) {
                const float* __restrict__ tr = &trow[u * 192];
                float na = 0.f, da = 0.f;
#pragma unroll 2
                for (int k = h; k < cnt; k += 8) {
                    float4 sy = g_msyn[m * CAPM + k];
                    float vp = tr[g_mtix[m * CAPM + k]];
                    float sg = rcpf(1.f + ex2f(fmaf(-sy.x, vp, sy.y)));
                    da = fmaf(sy.z, sg, da); na = fmaf(sy.w, sg, na);
                }
                na += __shfl_xor_sync(0xffffffffu, na, 1);
                na += __shfl_xor_sync(0xffffffffu, na, 2);
                na += __shfl_xor_sync(0xffffffffu, na, 4);
                da += __shfl_xor_sync(0xffffffffu, da, 1);
                da += __shfl_xor_sync(0xffffffffu, da, 2);
                da += __shfl_xor_sync(0xffffffffu, da, 4);
                if (h == 0) {
                    float2 ssm = g_ssum[it * 96 + m];
                    float dinv = rcpf(cmt + gl + ssm.y + da + EPSF);
                    g_mac[(it * UNF + u) * MOTORN + m] =
                        make_float2(cmt * dinv, (fmaf(gl, vl, ssm.x) + na) * dinv);
                }
            }
            __syncthreads();
        }
    }
    grid_barrier();   // #6

    // ================= P5: motor scans + output GEMV (blocks 0..31) ==========
    if (bx < NB && t < 32) {
        const int b = bx;
        const float ow = output_w[t], ob = output_b[t];
        const float db = dense_b[t];
        for (int i = t; i < MOTORN * OUTL; i += 32) sdw[i] = dense_w[i];
        __syncwarp();
        float v = 0.f;
        for (int s = 0; s < NT; s++) {
#pragma unroll
            for (int u = 0; u < UNF; u++) {
                float2 ac = g_mac[((b * NT + s) * UNF + u) * MOTORN + t];
                v = fmaf(ac.x, v, ac.y);
            }
            ym[t] = fmaf(v, ow, ob);
            __syncwarp();
            float acc = db;
#pragma unroll
            for (int m = 0; m < MOTORN; m++)
                acc = fmaf(ym[m], sdw[m * OUTL + t], acc);
            out[(b * NT + s) * OUTL + t] = acc;
            __syncwarp();
        }
    }
}

extern "C" void kernel_launch(void* const* d_in, const int* in_sizes, int n_in,
                              void* d_out, int out_size)
{
    const float* inputs   = (const float*)d_in[0];
    const float* input_w  = (const float*)d_in[1];
    const float* input_b  = (const float*)d_in[2];
    const float* smu      = (const float*)d_in[3];
    const float* ssig     = (const float*)d_in[4];
    const float* swt      = (const float*)d_in[5];
    const float* serev    = (const float*)d_in[6];
    const float* smask    = (const float*)d_in[7];
    const float* mu       = (const float*)d_in[8];
    const float* sig      = (const float*)d_in[9];
    const float* wt       = (const float*)d_in[10];
    const float* erev     = (const float*)d_in[11];
    const float* mask     = (const float*)d_in[12];
    const float* gleak    = (const float*)d_in[13];
    const float* vleak    = (const float*)d_in[14];
    const float* cm       = (const float*)d_in[15];
    const float* output_w = (const float*)d_in[16];
    const float* output_b = (const float*)d_in[17];
    const float* dense_w  = (const float*)d_in[18];
    const float* dense_b  = (const float*)d_in[19];
    float* out = (float*)d_out;

    ncp_persistent<<<NBLK, NTH>>>(inputs, input_w, input_b,
                                  smu, ssig, swt, serev, smask,
                                  mu, sig, wt, erev, mask,
                                  gleak, vleak, cm,
                                  output_w, output_b, dense_w, dense_b, out);
}

// round 6
// speedup vs baseline: 1.1322x; 1.0559x over previous
#include <cuda_runtime.h>

#define UNITS  224
#define SENS   64
#define MOTORN 32
#define CMDN   64
#define INTERN 128
#define OUTL   32
#define NB     32
#define NT     32
#define UNF    6
#define CAPS   32
#define CAPI   64
#define CAPC   16
#define CAPM   32
#define NBLK   148
#define NTH    256
#define P4BLK  116      // blocks 32..147
#define LOG2E  1.4426950408889634f
#define EPSF   1e-8f

// ---------------- compacted tables ----------------
__device__ float4 g_ssyn [UNITS * CAPS];
__device__ int    g_sidx [UNITS * CAPS];
__device__ int    g_scnt [UNITS];
__device__ float4 g_cisyn[CMDN * CAPI];
__device__ int    g_ciix [CMDN * CAPI];
__device__ int    g_cic  [CMDN];
__device__ float4 g_ccsyn[CMDN * CAPC];
__device__ int    g_ccix [CMDN * CAPC];
__device__ int    g_ccc  [CMDN];
__device__ float4 g_msyn [MOTORN * CAPM];
__device__ int    g_mtix [MOTORN * CAPM];
__device__ int    g_mc   [MOTORN];
__device__ int    g_badv [UNITS];

// ---------------- scratch ----------------
__device__ float2 g_ssum [NB * NT * 96];
__device__ float2 g_iac  [NB * NT * INTERN];
__device__ float  g_vtraj[NB * NT * UNF * INTERN];
__device__ float2 g_pcmd [NB * NT * UNF * CMDN];
__device__ float  g_ctraj[NB * NT * UNF * CMDN];
__device__ float2 g_mac  [NB * NT * UNF * MOTORN];

// monotonic counters (never reset; replay-safe via g_runs epoch)
__device__ unsigned g_arrive;
__device__ unsigned g_runs;
__device__ unsigned g_done  [NB];   // P2 items per batch (32/run)
__device__ unsigned g_p3done[NB];   // 1/run
__device__ unsigned g_p4done[NB];   // 32/run

__device__ __forceinline__ float ex2f(float x) {
    float r; asm("ex2.approx.ftz.f32 %0, %1;" : "=f"(r) : "f"(x)); return r;
}
__device__ __forceinline__ float rcpf(float x) {
    float r; asm("rcp.approx.ftz.f32 %0, %1;" : "=f"(r) : "f"(x)); return r;
}

__device__ __forceinline__ void grid_barrier() {
    __syncthreads();
    if (threadIdx.x == 0) {
        __threadfence();
        unsigned old = atomicAdd(&g_arrive, 1u);
        unsigned target = (old / NBLK + 1u) * NBLK;
        while (atomicAdd(&g_arrive, 0u) < target) { __nanosleep(64); }
        __threadfence();
    }
    __syncthreads();
}

__device__ __forceinline__ void wait_ge(unsigned* ctr, unsigned target) {
    if (threadIdx.x == 0) {
        while (atomicAdd(ctr, 0u) < target) { __nanosleep(32); }
        __threadfence();
    }
    __syncthreads();
}
__device__ __forceinline__ void signal(unsigned* ctr) {
    __syncthreads();
    if (threadIdx.x == 0) { __threadfence(); atomicAdd(ctr, 1u); }
}

__global__ void __launch_bounds__(NTH, 1)
ncp_persistent(
    const float* __restrict__ inputs,
    const float* __restrict__ input_w, const float* __restrict__ input_b,
    const float* __restrict__ smu,  const float* __restrict__ ssig,
    const float* __restrict__ swt,  const float* __restrict__ serev,
    const float* __restrict__ smask,
    const float* __restrict__ mu,   const float* __restrict__ sig,
    const float* __restrict__ wt,   const float* __restrict__ erev,
    const float* __restrict__ mask,
    const float* __restrict__ gleak, const float* __restrict__ vleak,
    const float* __restrict__ cm,
    const float* __restrict__ output_w, const float* __restrict__ output_b,
    const float* __restrict__ dense_w,  const float* __restrict__ dense_b,
    float* __restrict__ out)
{
    __shared__ float  sx[SENS];
    __shared__ float  vr[UNF * INTERN];
    __shared__ float  trow[UNF * 192];
    __shared__ float  vrow[CMDN];
    __shared__ float  ym[MOTORN];
    __shared__ float  sdw[MOTORN * OUTL];
    __shared__ float4 ccsynS[CMDN * CAPC];
    __shared__ int    ccixS [CMDN * CAPC];
    __shared__ float  fb0[UNITS], fb1[UNITS];

    const int t    = threadIdx.x;
    const int bx   = blockIdx.x;
    const int wid  = t >> 5;
    const int lane = t & 31;

    if (bx == 0 && t == 0) atomicAdd(&g_runs, 1u);

    // ================= P0: prep (one warp per post column) =================
    {
        const unsigned FULL = 0xffffffffu;
        const unsigned lt = (1u << lane) - 1u;
        const int j = bx * 8 + wid;
        if (j < UNITS) {
            int bad = 0;
            if (j < MOTORN) {
                int cnt = 0;
                for (int i0 = 0; i0 < UNITS; i0 += 32) {
                    int i = i0 + lane, gi = i * UNITS + j;
                    float m = mask[gi];
                    bool act = (m != 0.f);
                    if (act && i < MOTORN) bad = 1;
                    unsigned bal = __ballot_sync(FULL, act);
                    if (act) {
                        int pos = cnt + __popc(bal & lt);
                        if (pos < CAPM && i >= MOTORN) {
                            float sg = sig[gi]; float wm = wt[gi] * m;
                            g_msyn[j * CAPM + pos] =
                                make_float4(sg * LOG2E, sg * mu[gi] * LOG2E, wm, wm * erev[gi]);
                            g_mtix[j * CAPM + pos] = i - MOTORN;
                        }
                    }
                    cnt += __popc(bal);
                }
                if (cnt > CAPM) bad = 1;
                if (lane == 0) g_mc[j] = cnt;
            } else if (j < MOTORN + CMDN) {
                const int c = j - MOTORN;
                int icnt = 0, ccnt = 0;
                for (int i0 = 0; i0 < UNITS; i0 += 32) {
                    int i = i0 + lane, gi = i * UNITS + j;
                    float m = mask[gi];
                    bool act = (m != 0.f);
                    if (act && i < MOTORN) bad = 1;
                    bool isI = act && (i >= MOTORN + CMDN);
                    bool isC = act && (i >= MOTORN) && (i < MOTORN + CMDN);
                    unsigned balI = __ballot_sync(FULL, isI);
                    unsigned balC = __ballot_sync(FULL, isC);
                    if (isI) {
                        int pos = icnt + __popc(balI & lt);
                        if (pos < CAPI) {
                            float sg = sig[gi]; float wm = wt[gi] * m;
                            g_cisyn[c * CAPI + pos] =
                                make_float4(sg * LOG2E, sg * mu[gi] * LOG2E, wm, wm * erev[gi]);
                            g_ciix[c * CAPI + pos] = i - (MOTORN + CMDN);
                        }
                    }
                    if (isC) {
                        int pos = ccnt + __popc(balC & lt);
                        if (pos < CAPC) {
                            float sg = sig[gi]; float wm = wt[gi] * m;
                            g_ccsyn[c * CAPC + pos] =
                                make_float4(sg * LOG2E, sg * mu[gi] * LOG2E, wm, wm * erev[gi]);
                            g_ccix[c * CAPC + pos] = i - MOTORN;
                        }
                    }
                    icnt += __popc(balI);
                    ccnt += __popc(balC);
                }
                if (icnt > CAPI || ccnt > CAPC) bad = 1;
                if (lane == 0) { g_cic[c] = icnt; g_ccc[c] = ccnt; }
            } else {
                for (int i0 = 0; i0 < UNITS; i0 += 32)
                    if (mask[(i0 + lane) * UNITS + j] != 0.f) bad = 1;
            }
            int cnt = 0;
            for (int i0 = 0; i0 < SENS; i0 += 32) {
                int i = i0 + lane, gi = i * UNITS + j;
                float m = smask[gi];
                bool act = (m != 0.f);
                unsigned bal = __ballot_sync(FULL, act);
                if (act) {
                    int pos = cnt + __popc(bal & lt);
                    if (pos < CAPS) {
                        float sg = ssig[gi]; float wm = swt[gi] * m;
                        g_ssyn[j * CAPS + pos] =
                            make_float4(sg * LOG2E, sg * smu[gi] * LOG2E, wm, wm * serev[gi]);
                        g_sidx[j * CAPS + pos] = i;
                    }
                }
                cnt += __popc(bal);
            }
            if (cnt > CAPS) bad = 1;
            if (lane == 0) g_scnt[j] = cnt;
            bad = (__ballot_sync(FULL, bad) != 0u);
            if (lane == 0) g_badv[j] = bad;
        }
    }
    grid_barrier();   // #1

    const unsigned runs = g_runs;   // stable after barrier
    const int anybad = __syncthreads_or((t < UNITS) ? g_badv[t] : 0);

    if (anybad) {
        // ============== DENSE FALLBACK (blocks 0..31, any wiring) ==============
        if (bx < NB) {
            const int b = bx, j = t;
            float cmt = 0.f, gl = 0.f, gv = 0.f;
            if (j < UNITS) {
                cmt = cm[j] * (float)UNF; gl = gleak[j]; gv = gl * vleak[j];
                fb0[j] = 0.f;
            }
            for (int i = t; i < MOTORN * OUTL; i += NTH) sdw[i] = dense_w[i];
            __syncthreads();
            float* cur = fb0; float* nxt = fb1;
            for (int s = 0; s < NT; s++) {
                if (t < SENS)
                    sx[t] = fmaf(inputs[(b * NT + s) * SENS + t], input_w[t], input_b[t]);
                __syncthreads();
                float sn = 0.f, sd = 0.f;
                if (j < UNITS) {
                    for (int i = 0; i < SENS; i++) {
                        float m = smask[i * UNITS + j];
                        if (m != 0.f) {
                            float sg = ssig[i * UNITS + j];
                            float sv = rcpf(1.f + ex2f(LOG2E * sg * (smu[i * UNITS + j] - sx[i])));
                            float wm = swt[i * UNITS + j] * m;
                            sd += wm * sv; sn += wm * serev[i * UNITS + j] * sv;
                        }
                    }
                }
                for (int u = 0; u < UNF; u++) {
                    float na = sn, da = sd;
                    if (j < UNITS) {
                        for (int i = 0; i < UNITS; i++) {
                            float m = mask[i * UNITS + j];
                            if (m != 0.f) {
                                float sg = sig[i * UNITS + j];
                                float sv = rcpf(1.f + ex2f(LOG2E * sg * (mu[i * UNITS + j] - cur[i])));
                                float wm = wt[i * UNITS + j] * m;
                                da += wm * sv; na += wm * erev[i * UNITS + j] * sv;
                            }
                        }
                        nxt[j] = (fmaf(cmt, cur[j], gv) + na) * rcpf(cmt + gl + da + EPSF);
                    }
                    __syncthreads();
                    float* tmp = cur; cur = nxt; nxt = tmp;
                }
                if (t < OUTL) {
                    float acc = dense_b[t];
                    for (int m = 0; m < MOTORN; m++)
                        acc = fmaf(fmaf(cur[m], output_w[m], output_b[m]),
                                   sdw[m * OUTL + t], acc);
                    out[(b * NT + s) * OUTL + t] = acc;
                }
                __syncthreads();
            }
        }
        return;
    }

    // ================= P1: sensory sums + inter affine coeffs =================
    for (int it = bx; it < NB * NT; it += NBLK) {
        if (t < SENS)
            sx[t] = fmaf(inputs[it * SENS + t], input_w[t], input_b[t]);
        __syncthreads();
        if (t < UNITS) {
            const int scnt = g_scnt[t];
            float sn = 0.f, sd = 0.f;
#pragma unroll 4
            for (int k = 0; k < scnt; k++) {
                float4 sy = g_ssyn[t * CAPS + k];
                float x = sx[g_sidx[t * CAPS + k]];
                float sg = rcpf(1.f + ex2f(fmaf(-sy.x, x, sy.y)));
                sd = fmaf(sy.z, sg, sd); sn = fmaf(sy.w, sg, sn);
            }
            if (t < MOTORN + CMDN) {
                g_ssum[it * 96 + t] = make_float2(sn, sd);
            } else {
                float cmt = cm[t] * (float)UNF;
                float gl = gleak[t];
                float dinv = rcpf(cmt + gl + sd + EPSF);
                g_iac[it * INTERN + (t - 96)] =
                    make_float2(cmt * dinv, fmaf(gl, vleak[t], sn) * dinv);
            }
        }
        __syncthreads();
    }
    grid_barrier();   // #2

    // ================= P1.5: inter scans (blocks 0..31, coalesced) =============
    if (bx < NB && t < INTERN) {
        const int b = bx;
        float v = 0.f;
        for (int s = 0; s < NT; s++) {
            float2 ac = g_iac[(b * NT + s) * INTERN + t];
#pragma unroll
            for (int u = 0; u < UNF; u++) {
                g_vtraj[((b * NT + s) * UNF + u) * INTERN + t] = v;
                v = fmaf(ac.x, v, ac.y);
            }
        }
    }
    grid_barrier();   // #3

    // ================= P2: cmd <- inter partials (all blocks, flagged) ========
    {
        const int c = t >> 2, h = t & 3;
        const int cnt = g_cic[c];
        for (int it = bx; it < NB * NT; it += NBLK) {
            for (int idx = t; idx < UNF * INTERN; idx += NTH)
                vr[idx] = g_vtraj[it * (UNF * INTERN) + idx];
            __syncthreads();
#pragma unroll
            for (int u = 0; u < UNF; u++) {
                const float* __restrict__ vrw = &vr[u * INTERN];
                float na = 0.f, da = 0.f;
#pragma unroll 4
                for (int k = h; k < cnt; k += 4) {
                    float4 sy = g_cisyn[c * CAPI + k];
                    float vp = vrw[g_ciix[c * CAPI + k]];
                    float sg = rcpf(1.f + ex2f(fmaf(-sy.x, vp, sy.y)));
                    da = fmaf(sy.z, sg, da); na = fmaf(sy.w, sg, na);
                }
                na += __shfl_xor_sync(0xffffffffu, na, 1);
                na += __shfl_xor_sync(0xffffffffu, na, 2);
                da += __shfl_xor_sync(0xffffffffu, da, 1);
                da += __shfl_xor_sync(0xffffffffu, da, 2);
                if (h == 0) g_pcmd[(it * UNF + u) * CMDN + c] = make_float2(na, da);
            }
            signal(&g_done[it >> 5]);   // includes __syncthreads
        }
    }

    if (bx < NB) {
        // ============ P3: sequential cmd scan for batch bx (warp 0) ============
        for (int i = t; i < CMDN * CAPC; i += NTH) {
            ccsynS[i] = g_ccsyn[i];
            ccixS[i]  = g_ccix[i];
        }
        wait_ge(&g_done[bx], runs * 32u);

        if (t < 32) {
            const int b = bx;
            const int p0 = 2 * t, p1 = 2 * t + 1;
            const int j0 = MOTORN + p0, j1 = MOTORN + p1;
            const float cmt0 = cm[j0] * (float)UNF, cmt1 = cm[j1] * (float)UNF;
            const float gl0 = gleak[j0], gl1 = gleak[j1];
            const float gv0 = gl0 * vleak[j0], gv1 = gl1 * vleak[j1];
            const int cc0 = g_ccc[p0], cc1 = g_ccc[p1];
            float v0 = 0.f, v1 = 0.f;

            float2 ss0 = g_ssum[(b * NT) * 96 + j0];
            float2 ss1 = g_ssum[(b * NT) * 96 + j1];
            float2 pc0 = g_pcmd[(b * NT * UNF) * CMDN + p0];
            float2 pc1 = g_pcmd[(b * NT * UNF) * CMDN + p1];

            for (int s = 0; s < NT; s++) {
                const int sn1 = (s + 1 < NT) ? s + 1 : s;
                float2 nss0 = g_ssum[(b * NT + sn1) * 96 + j0];
                float2 nss1 = g_ssum[(b * NT + sn1) * 96 + j1];
                const float cn0 = gv0 + ss0.x, cd0 = cmt0 + gl0 + ss0.y + EPSF;
                const float cn1 = gv1 + ss1.x, cd1 = cmt1 + gl1 + ss1.y + EPSF;
#pragma unroll
                for (int u = 0; u < UNF; u++) {
                    ((float2*)vrow)[t] = make_float2(v0, v1);
                    const int row = ((b * NT + s) * UNF + u) * CMDN;
                    ((float2*)(g_ctraj + row))[t] = make_float2(v0, v1);
                    __syncwarp();
                    int nu = (u < UNF - 1) ? u + 1 : 0;
                    int ns = (u < UNF - 1) ? s : sn1;
                    const int nrow = ((b * NT + ns) * UNF + nu) * CMDN;
                    float2 npc0 = g_pcmd[nrow + p0];
                    float2 npc1 = g_pcmd[nrow + p1];
                    float na0 = 0.f, da0 = 0.f, na1 = 0.f, da1 = 0.f;
                    for (int k = 0; k < cc0; k++) {
                        float4 sy = ccsynS[p0 * CAPC + k];
                        float vp = vrow[ccixS[p0 * CAPC + k]];
                        float sg = rcpf(1.f + ex2f(fmaf(-sy.x, vp, sy.y)));
                        da0 = fmaf(sy.z, sg, da0); na0 = fmaf(sy.w, sg, na0);
                    }
                    for (int k = 0; k < cc1; k++) {
                        float4 sy = ccsynS[p1 * CAPC + k];
                        float vp = vrow[ccixS[p1 * CAPC + k]];
                        float sg = rcpf(1.f + ex2f(fmaf(-sy.x, vp, sy.y)));
                        da1 = fmaf(sy.z, sg, da1); na1 = fmaf(sy.w, sg, na1);
                    }
                    v0 = (fmaf(cmt0, v0, cn0) + pc0.x + na0) * rcpf(cd0 + pc0.y + da0);
                    v1 = (fmaf(cmt1, v1, cn1) + pc1.x + na1) * rcpf(cd1 + pc1.y + da1);
                    pc0 = npc0; pc1 = npc1;
                    __syncwarp();
                }
                ss0 = nss0; ss1 = nss1;
            }
        }
        signal(&g_p3done[bx]);

        // ============ P5: motor scan + output GEMV for batch bx ===============
        for (int i = t; i < MOTORN * OUTL; i += NTH) sdw[i] = dense_w[i];
        wait_ge(&g_p4done[bx], runs * 32u);
        if (t < 32) {
            const int b = bx;
            const float ow = output_w[t], ob = output_b[t];
            const float db = dense_b[t];
            float v = 0.f;
            for (int s = 0; s < NT; s++) {
#pragma unroll
                for (int u = 0; u < UNF; u++) {
                    float2 ac = g_mac[((b * NT + s) * UNF + u) * MOTORN + t];
                    v = fmaf(ac.x, v, ac.y);
                }
                ym[t] = fmaf(v, ow, ob);
                __syncwarp();
                float acc = db;
#pragma unroll
                for (int m = 0; m < MOTORN; m++)
                    acc = fmaf(ym[m], sdw[m * OUTL + t], acc);
                out[(b * NT + s) * OUTL + t] = acc;
                __syncwarp();
            }
        }
    } else {
        // ============ P4: motor partials (blocks 32..147, flagged) =============
        const int m = t >> 3, h = t & 7;
        const int cnt = g_mc[m];
        const float cmt = cm[m] * (float)UNF;
        const float gl = gleak[m];
        const float vl = vleak[m];
        for (int it = bx - NB; it < NB * NT; it += P4BLK) {
            wait_ge(&g_p3done[it >> 5], runs);
            for (int idx = t; idx < UNF * CMDN; idx += NTH) {
                int u = idx >> 6, c = idx & 63;
                trow[u * 192 + c] = g_ctraj[(it * UNF + u) * CMDN + c];
            }
            for (int idx = t; idx < UNF * INTERN; idx += NTH) {
                int u = idx >> 7, i = idx & 127;
                trow[u * 192 + CMDN + i] = g_vtraj[it * (UNF * INTERN) + idx];
            }
            __syncthreads();
#pragma unroll
            for (int u = 0; u < UNF; u++) {
                const float* __restrict__ tr = &trow[u * 192];
                float na = 0.f, da = 0.f;
#pragma unroll 2
                for (int k = h; k < cnt; k += 8) {
                    float4 sy = g_msyn[m * CAPM + k];
                    float vp = tr[g_mtix[m * CAPM + k]];
                    float sg = rcpf(1.f + ex2f(fmaf(-sy.x, vp, sy.y)));
                    da = fmaf(sy.z, sg, da); na = fmaf(sy.w, sg, na);
                }
                na += __shfl_xor_sync(0xffffffffu, na, 1);
                na += __shfl_xor_sync(0xffffffffu, na, 2);
                na += __shfl_xor_sync(0xffffffffu, na, 4);
                da += __shfl_xor_sync(0xffffffffu, da, 1);
                da += __shfl_xor_sync(0xffffffffu, da, 2);
                da += __shfl_xor_sync(0xffffffffu, da, 4);
                if (h == 0) {
                    float2 ssm = g_ssum[(it) * 96 + m];
                    float dinv = rcpf(cmt + gl + ssm.y + da + EPSF);
                    g_mac[(it * UNF + u) * MOTORN + m] =
                        make_float2(cmt * dinv, (fmaf(gl, vl, ssm.x) + na) * dinv);
                }
            }
            signal(&g_p4done[it >> 5]);   // includes __syncthreads
        }
    }
}

extern "C" void kernel_launch(void* const* d_in, const int* in_sizes, int n_in,
                              void* d_out, int out_size)
{
    const float* inputs   = (const float*)d_in[0];
    const float* input_w  = (const float*)d_in[1];
    const float* input_b  = (const float*)d_in[2];
    const float* smu      = (const float*)d_in[3];
    const float* ssig     = (const float*)d_in[4];
    const float* swt      = (const float*)d_in[5];
    const float* serev    = (const float*)d_in[6];
    const float* smask    = (const float*)d_in[7];
    const float* mu       = (const float*)d_in[8];
    const float* sig      = (const float*)d_in[9];
    const float* wt       = (const float*)d_in[10];
    const float* erev     = (const float*)d_in[11];
    const float* mask     = (const float*)d_in[12];
    const float* gleak    = (const float*)d_in[13];
    const float* vleak    = (const float*)d_in[14];
    const float* cm       = (const float*)d_in[15];
    const float* output_w = (const float*)d_in[16];
    const float* output_b = (const float*)d_in[17];
    const float* dense_w  = (const float*)d_in[18];
    const float* dense_b  = (const float*)d_in[19];
    float* out = (float*)d_out;

    ncp_persistent<<<NBLK, NTH>>>(inputs, input_w, input_b,
                                  smu, ssig, swt, serev, smask,
                                  mu, sig, wt, erev, mask,
                                  gleak, vleak, cm,
                                  output_w, output_b, dense_w, dense_b, out);
}

// round 7
// speedup vs baseline: 1.9171x; 1.6933x over previous
#include <cuda_runtime.h>

#define UNITS  224
#define SENS   64
#define MOTORN 32
#define CMDN   64
#define INTERN 128
#define OUTL   32
#define NB     32
#define NT     32
#define UNF    6
#define CAPS   32
#define CAPI   64
#define CAPC   16
#define CAPM   32
#define LOG2E  1.4426950408889634f
#define EPSF   1e-8f

// ---------------- compacted tables (rebuilt every launch) ----------------
__device__ float4 g_ssyn [UNITS * CAPS];
__device__ int    g_sidx [UNITS * CAPS];
__device__ int    g_scnt [UNITS];
__device__ float4 g_cisyn[CMDN * CAPI];
__device__ int    g_ciix [CMDN * CAPI];
__device__ int    g_cic  [CMDN];
__device__ float4 g_ccsyn[CMDN * CAPC];
__device__ int    g_ccix [CMDN * CAPC];
__device__ int    g_ccc  [CMDN];
__device__ float4 g_msyn [MOTORN * CAPM];
__device__ int    g_mtix [MOTORN * CAPM];
__device__ int    g_mc   [MOTORN];
__device__ int    g_badv [UNITS];

// ---------------- scratch ----------------
__device__ float2 g_ssum [NB * NT * 96];
__device__ float2 g_iac  [NB * NT * INTERN];
__device__ float  g_vtraj[NB * NT * UNF * INTERN];
__device__ float2 g_pcmd [NB * NT * UNF * CMDN];
__device__ float  g_ctraj[NB * NT * UNF * CMDN];
__device__ float2 g_mac  [NB * NT * UNF * MOTORN];

__device__ __forceinline__ float ex2f(float x) {
    float r; asm("ex2.approx.ftz.f32 %0, %1;" : "=f"(r) : "f"(x)); return r;
}
__device__ __forceinline__ float rcpf(float x) {
    float r; asm("rcp.approx.ftz.f32 %0, %1;" : "=f"(r) : "f"(x)); return r;
}

// ======================= prep: one warp per post column =======================
__global__ void kprep(
    const float* __restrict__ smu,  const float* __restrict__ ssig,
    const float* __restrict__ swt,  const float* __restrict__ serev,
    const float* __restrict__ smask,
    const float* __restrict__ mu,   const float* __restrict__ sig,
    const float* __restrict__ wt,   const float* __restrict__ erev,
    const float* __restrict__ mask)
{
    const int j = blockIdx.x;
    const int lane = threadIdx.x;
    const unsigned FULL = 0xffffffffu;
    const unsigned lt = (1u << lane) - 1u;
    int bad = 0;

    float mv[7];
#pragma unroll
    for (int r = 0; r < 7; r++) mv[r] = mask[(r * 32 + lane) * UNITS + j];
    float sv[2];
#pragma unroll
    for (int r = 0; r < 2; r++) sv[r] = smask[(r * 32 + lane) * UNITS + j];

    if (j < MOTORN) {
        int cnt = 0;
#pragma unroll
        for (int r = 0; r < 7; r++) {
            const int i = r * 32 + lane, gi = i * UNITS + j;
            const bool act = (mv[r] != 0.f);
            if (act && i < MOTORN) bad = 1;
            unsigned bal = __ballot_sync(FULL, act);
            if (act) {
                int pos = cnt + __popc(bal & lt);
                if (pos < CAPM && i >= MOTORN) {
                    float sg = sig[gi], wm = wt[gi] * mv[r];
                    g_msyn[j * CAPM + pos] =
                        make_float4(sg * LOG2E, sg * mu[gi] * LOG2E, wm, wm * erev[gi]);
                    g_mtix[j * CAPM + pos] = i - MOTORN;
                }
            }
            cnt += __popc(bal);
        }
        if (cnt > CAPM) bad = 1;
        if (lane == 0) g_mc[j] = cnt;
    } else if (j < MOTORN + CMDN) {
        const int c = j - MOTORN;
        int icnt = 0, ccnt = 0;
#pragma unroll
        for (int r = 0; r < 7; r++) {
            const int i = r * 32 + lane, gi = i * UNITS + j;
            const bool act = (mv[r] != 0.f);
            if (act && i < MOTORN) bad = 1;
            const bool isI = act && (i >= MOTORN + CMDN);
            const bool isC = act && (i >= MOTORN) && (i < MOTORN + CMDN);
            unsigned balI = __ballot_sync(FULL, isI);
            unsigned balC = __ballot_sync(FULL, isC);
            if (isI) {
                int pos = icnt + __popc(balI & lt);
                if (pos < CAPI) {
                    float sg = sig[gi], wm = wt[gi] * mv[r];
                    g_cisyn[c * CAPI + pos] =
                        make_float4(sg * LOG2E, sg * mu[gi] * LOG2E, wm, wm * erev[gi]);
                    g_ciix[c * CAPI + pos] = i - (MOTORN + CMDN);
                }
            }
            if (isC) {
                int pos = ccnt + __popc(balC & lt);
                if (pos < CAPC) {
                    float sg = sig[gi], wm = wt[gi] * mv[r];
                    g_ccsyn[c * CAPC + pos] =
                        make_float4(sg * LOG2E, sg * mu[gi] * LOG2E, wm, wm * erev[gi]);
                    g_ccix[c * CAPC + pos] = i - MOTORN;
                }
            }
            icnt += __popc(balI);
            ccnt += __popc(balC);
        }
        if (icnt > CAPI || ccnt > CAPC) bad = 1;
        // zero-pad cmd<-cmd table (kp3 reads padded entries)
        for (int pos = ccnt + lane; pos < CAPC; pos += 32) {
            g_ccsyn[c * CAPC + pos] = make_float4(0.f, 0.f, 0.f, 0.f);
            g_ccix[c * CAPC + pos] = 0;
        }
        if (lane == 0) { g_cic[c] = icnt; g_ccc[c] = ccnt; }
    } else {
#pragma unroll
        for (int r = 0; r < 7; r++)
            if (mv[r] != 0.f) bad = 1;   // inter posts must be recurrent-free
    }

    // sensory table (all posts)
    int cnt = 0;
#pragma unroll
    for (int r = 0; r < 2; r++) {
        const int i = r * 32 + lane, gi = i * UNITS + j;
        const bool act = (sv[r] != 0.f);
        unsigned bal = __ballot_sync(FULL, act);
        if (act) {
            int pos = cnt + __popc(bal & lt);
            if (pos < CAPS) {
                float sg = ssig[gi], wm = swt[gi] * sv[r];
                g_ssyn[j * CAPS + pos] =
                    make_float4(sg * LOG2E, sg * smu[gi] * LOG2E, wm, wm * serev[gi]);
                g_sidx[j * CAPS + pos] = i;
            }
        }
        cnt += __popc(bal);
    }
    if (cnt > CAPS) bad = 1;
    if (lane == 0) g_scnt[j] = cnt;

    bad = (__ballot_sync(FULL, bad) != 0u);
    if (lane == 0) g_badv[j] = bad;
}

// ============ P1: per-(b,s) sensory sums + inter affine coeffs (grid 1024) ====
__global__ void __launch_bounds__(256)
kp1(const float* __restrict__ inputs,
    const float* __restrict__ input_w, const float* __restrict__ input_b,
    const float* __restrict__ gleak, const float* __restrict__ vleak,
    const float* __restrict__ cm)
{
    __shared__ float sx[SENS];
    const int bs = blockIdx.x;
    const int t = threadIdx.x;
    if (t < SENS)
        sx[t] = fmaf(inputs[bs * SENS + t], input_w[t], input_b[t]);
    __syncthreads();
    if (t < UNITS) {
        const int scnt = min(g_scnt[t], CAPS);
        float sn = 0.f, sd = 0.f;
#pragma unroll 4
        for (int k = 0; k < scnt; k++) {
            float4 sy = g_ssyn[t * CAPS + k];
            float x = sx[g_sidx[t * CAPS + k]];
            float sg = rcpf(1.f + ex2f(fmaf(-sy.x, x, sy.y)));
            sd = fmaf(sy.z, sg, sd); sn = fmaf(sy.w, sg, sn);
        }
        if (t < MOTORN + CMDN) {
            g_ssum[bs * 96 + t] = make_float2(sn, sd);
        } else {
            float cmt = cm[t] * (float)UNF;
            float gl  = gleak[t];
            float dinv = rcpf(cmt + gl + sd + EPSF);
            g_iac[bs * INTERN + (t - 96)] =
                make_float2(cmt * dinv, fmaf(gl, vleak[t], sn) * dinv);
        }
    }
}

// ============ inter affine scans: grid 32 x 128 ==============================
__global__ void __launch_bounds__(INTERN)
kiscan()
{
    const int b = blockIdx.x, i = threadIdx.x;
    float v = 0.f;
    float2 ac = g_iac[(b * NT) * INTERN + i];
    for (int s = 0; s < NT; s++) {
        const int sn = (s + 1 < NT) ? s + 1 : s;
        float2 nac = g_iac[(b * NT + sn) * INTERN + i];
        const int base = ((b * NT + s) * UNF) * INTERN + i;
#pragma unroll
        for (int u = 0; u < UNF; u++) {
            g_vtraj[base + u * INTERN] = v;
            v = fmaf(ac.x, v, ac.y);
        }
        ac = nac;
    }
}

// ============ P2: cmd <- inter partials: grid 1024 x 256 =====================
__global__ void __launch_bounds__(256)
kp2()
{
    __shared__ float vr[UNF * INTERN];
    const int bs = blockIdx.x;
    const int t = threadIdx.x;
    for (int i = t; i < UNF * INTERN; i += 256)
        vr[i] = g_vtraj[bs * (UNF * INTERN) + i];
    __syncthreads();
    const int c = t >> 2, h = t & 3;
    const int cnt = min(g_cic[c], CAPI);
#pragma unroll
    for (int u = 0; u < UNF; u++) {
        const float* __restrict__ vrw = &vr[u * INTERN];
        float na = 0.f, da = 0.f;
#pragma unroll 4
        for (int k = h; k < cnt; k += 4) {
            float4 sy = g_cisyn[c * CAPI + k];
            float vp = vrw[g_ciix[c * CAPI + k]];
            float sg = rcpf(1.f + ex2f(fmaf(-sy.x, vp, sy.y)));
            da = fmaf(sy.z, sg, da); na = fmaf(sy.w, sg, na);
        }
        na += __shfl_xor_sync(0xffffffffu, na, 1);
        na += __shfl_xor_sync(0xffffffffu, na, 2);
        da += __shfl_xor_sync(0xffffffffu, da, 1);
        da += __shfl_xor_sync(0xffffffffu, da, 2);
        if (h == 0) g_pcmd[(bs * UNF + u) * CMDN + c] = make_float2(na, da);
    }
}

// ============ P3: sequential command core: grid 32 x 32, all-register =========
__global__ void __launch_bounds__(32)
kp3(const float* __restrict__ gleak, const float* __restrict__ vleak,
    const float* __restrict__ cm)
{
    const int b = blockIdx.x;
    const int l = threadIdx.x;
    const unsigned FULL = 0xffffffffu;
    const int p0 = l, p1 = 32 + l;        // cmd-local posts this lane owns
    const int j0 = MOTORN + p0, j1 = MOTORN + p1;
    const float cmt0 = cm[j0] * (float)UNF, cmt1 = cm[j1] * (float)UNF;
    const float gl0 = gleak[j0], gl1 = gleak[j1];
    const float gv0 = gl0 * vleak[j0], gv1 = gl1 * vleak[j1];
    const int cc0 = min(g_ccc[p0], CAPC), cc1 = min(g_ccc[p1], CAPC);

    float4 syA[8]; int ixA[8]; float4 syB[8]; int ixB[8];
#pragma unroll
    for (int k = 0; k < 8; k++) {
        syA[k] = g_ccsyn[p0 * CAPC + k]; ixA[k] = g_ccix[p0 * CAPC + k];
        syB[k] = g_ccsyn[p1 * CAPC + k]; ixB[k] = g_ccix[p1 * CAPC + k];
    }
    int cmx = max(cc0, cc1);
    for (int off = 16; off; off >>= 1)
        cmx = max(cmx, __shfl_xor_sync(FULL, cmx, off));
    const int cmreg = min(cmx, 8);

    float v0 = 0.f, v1 = 0.f;
    float2 pc0[UNF], pc1[UNF];
    float2 ss0 = g_ssum[(b * NT) * 96 + j0];
    float2 ss1 = g_ssum[(b * NT) * 96 + j1];
#pragma unroll
    for (int u = 0; u < UNF; u++) {
        pc0[u] = g_pcmd[((b * NT) * UNF + u) * CMDN + p0];
        pc1[u] = g_pcmd[((b * NT) * UNF + u) * CMDN + p1];
    }

    for (int s = 0; s < NT; s++) {
        const int sn = (s + 1 < NT) ? s + 1 : s;
        float2 nss0 = g_ssum[(b * NT + sn) * 96 + j0];
        float2 nss1 = g_ssum[(b * NT + sn) * 96 + j1];
        float2 npc0[UNF], npc1[UNF];
#pragma unroll
        for (int u = 0; u < UNF; u++) {
            npc0[u] = g_pcmd[((b * NT + sn) * UNF + u) * CMDN + p0];
            npc1[u] = g_pcmd[((b * NT + sn) * UNF + u) * CMDN + p1];
        }
        const float cn0 = gv0 + ss0.x, cd0 = cmt0 + gl0 + ss0.y + EPSF;
        const float cn1 = gv1 + ss1.x, cd1 = cmt1 + gl1 + ss1.y + EPSF;
#pragma unroll
        for (int u = 0; u < UNF; u++) {
            const int row = ((b * NT + s) * UNF + u) * CMDN;
            g_ctraj[row + p0] = v0;      // state entering unfold u
            g_ctraj[row + p1] = v1;
            float na0 = 0.f, da0 = 0.f, na1 = 0.f, da1 = 0.f;
#pragma unroll
            for (int k = 0; k < 8; k++) {
                if (k >= cmreg) break;   // cmreg warp-uniform
                {
                    const int q = ixA[k];
                    float a  = __shfl_sync(FULL, v0, q & 31);
                    float bb = __shfl_sync(FULL, v1, q & 31);
                    float vp = (q < 32) ? a : bb;
                    float sg = rcpf(1.f + ex2f(fmaf(-syA[k].x, vp, syA[k].y)));
                    da0 = fmaf(syA[k].z, sg, da0);
                    na0 = fmaf(syA[k].w, sg, na0);
                }
                {
                    const int q = ixB[k];
                    float a  = __shfl_sync(FULL, v0, q & 31);
                    float bb = __shfl_sync(FULL, v1, q & 31);
                    float vp = (q < 32) ? a : bb;
                    float sg = rcpf(1.f + ex2f(fmaf(-syB[k].x, vp, syB[k].y)));
                    da1 = fmaf(syB[k].z, sg, da1);
                    na1 = fmaf(syB[k].w, sg, na1);
                }
            }
            for (int k = 8; k < cmx; k++) {   // rare tail; cmx warp-uniform
                {
                    float4 sy = g_ccsyn[p0 * CAPC + k];
                    const int q = g_ccix[p0 * CAPC + k];
                    float a  = __shfl_sync(FULL, v0, q & 31);
                    float bb = __shfl_sync(FULL, v1, q & 31);
                    float vp = (q < 32) ? a : bb;
                    float sg = rcpf(1.f + ex2f(fmaf(-sy.x, vp, sy.y)));
                    da0 = fmaf(sy.z, sg, da0);
                    na0 = fmaf(sy.w, sg, na0);
                }
                {
                    float4 sy = g_ccsyn[p1 * CAPC + k];
                    const int q = g_ccix[p1 * CAPC + k];
                    float a  = __shfl_sync(FULL, v0, q & 31);
                    float bb = __shfl_sync(FULL, v1, q & 31);
                    float vp = (q < 32) ? a : bb;
                    float sg = rcpf(1.f + ex2f(fmaf(-sy.x, vp, sy.y)));
                    da1 = fmaf(sy.z, sg, da1);
                    na1 = fmaf(sy.w, sg, na1);
                }
            }
            v0 = (fmaf(cmt0, v0, cn0) + pc0[u].x + na0) * rcpf(cd0 + pc0[u].y + da0);
            v1 = (fmaf(cmt1, v1, cn1) + pc1[u].x + na1) * rcpf(cd1 + pc1[u].y + da1);
        }
#pragma unroll
        for (int u = 0; u < UNF; u++) { pc0[u] = npc0[u]; pc1[u] = npc1[u]; }
        ss0 = nss0; ss1 = nss1;
    }
}

// ============ P4: motor affine coeffs: grid 1024 x 256 =======================
__global__ void __launch_bounds__(256)
kp4(const float* __restrict__ gleak, const float* __restrict__ vleak,
    const float* __restrict__ cm)
{
    __shared__ float trow[UNF * 192];
    const int bs = blockIdx.x;
    const int t = threadIdx.x;
    for (int idx = t; idx < UNF * CMDN; idx += 256) {
        int u = idx >> 6, c = idx & 63;
        trow[u * 192 + c] = g_ctraj[(bs * UNF + u) * CMDN + c];
    }
    for (int idx = t; idx < UNF * INTERN; idx += 256) {
        int u = idx >> 7, i = idx & 127;
        trow[u * 192 + CMDN + i] = g_vtraj[bs * (UNF * INTERN) + idx];
    }
    __syncthreads();
    const int m = t >> 3, h = t & 7;
    const int cnt = min(g_mc[m], CAPM);
    const float cmt = cm[m] * (float)UNF;
    const float gl = gleak[m], vl = vleak[m];
    const float2 ssm = g_ssum[bs * 96 + m];
#pragma unroll
    for (int u = 0; u < UNF; u++) {
        const float* __restrict__ tr = &trow[u * 192];
        float na = 0.f, da = 0.f;
#pragma unroll 2
        for (int k = h; k < cnt; k += 8) {
            float4 sy = g_msyn[m * CAPM + k];
            float vp = tr[g_mtix[m * CAPM + k]];
            float sg = rcpf(1.f + ex2f(fmaf(-sy.x, vp, sy.y)));
            da = fmaf(sy.z, sg, da); na = fmaf(sy.w, sg, na);
        }
        na += __shfl_xor_sync(0xffffffffu, na, 1);
        na += __shfl_xor_sync(0xffffffffu, na, 2);
        na += __shfl_xor_sync(0xffffffffu, na, 4);
        da += __shfl_xor_sync(0xffffffffu, da, 1);
        da += __shfl_xor_sync(0xffffffffu, da, 2);
        da += __shfl_xor_sync(0xffffffffu, da, 4);
        if (h == 0) {
            float dinv = rcpf(cmt + gl + ssm.y + da + EPSF);
            g_mac[(bs * UNF + u) * MOTORN + m] =
                make_float2(cmt * dinv, (fmaf(gl, vl, ssm.x) + na) * dinv);
        }
    }
}

// ============ P5: motor scan + output GEMV: grid 8 x 128 (warp = batch) ======
__global__ void __launch_bounds__(128)
kp5(const float* __restrict__ output_w, const float* __restrict__ output_b,
    const float* __restrict__ dense_w,  const float* __restrict__ dense_b,
    float* __restrict__ out)
{
    int badl = 0;
    for (int i = threadIdx.x; i < UNITS; i += 128) badl |= g_badv[i];
    if (__syncthreads_or(badl)) return;

    const int w = threadIdx.x >> 5, lane = threadIdx.x & 31;
    const int b = blockIdx.x * 4 + w;
    const float ow = output_w[lane], ob = output_b[lane];
    const float db = dense_b[lane];
    float dwc[32];
#pragma unroll
    for (int m = 0; m < 32; m++) dwc[m] = dense_w[m * OUTL + lane];

    float v = 0.f;
    float2 mc[UNF];
#pragma unroll
    for (int u = 0; u < UNF; u++)
        mc[u] = g_mac[((b * NT) * UNF + u) * MOTORN + lane];

    for (int s = 0; s < NT; s++) {
        const int sn = (s + 1 < NT) ? s + 1 : s;
        float2 nmc[UNF];
#pragma unroll
        for (int u = 0; u < UNF; u++)
            nmc[u] = g_mac[((b * NT + sn) * UNF + u) * MOTORN + lane];
#pragma unroll
        for (int u = 0; u < UNF; u++) v = fmaf(mc[u].x, v, mc[u].y);
        float ym = fmaf(v, ow, ob);
        float acc = db;
#pragma unroll
        for (int m = 0; m < 32; m++)
            acc = fmaf(__shfl_sync(0xffffffffu, ym, m), dwc[m], acc);
        out[(b * NT + s) * OUTL + lane] = acc;
#pragma unroll
        for (int u = 0; u < UNF; u++) mc[u] = nmc[u];
    }
}

// ============ dense fallback (any wiring; early-exit when fast path valid) ====
__global__ void __launch_bounds__(UNITS)
kfall(
    const float* __restrict__ inputs,
    const float* __restrict__ input_w, const float* __restrict__ input_b,
    const float* __restrict__ smu,  const float* __restrict__ ssig,
    const float* __restrict__ swt,  const float* __restrict__ serev,
    const float* __restrict__ smask,
    const float* __restrict__ mu,   const float* __restrict__ sig,
    const float* __restrict__ wt,   const float* __restrict__ erev,
    const float* __restrict__ mask,
    const float* __restrict__ gleak, const float* __restrict__ vleak,
    const float* __restrict__ cm,
    const float* __restrict__ output_w, const float* __restrict__ output_b,
    const float* __restrict__ dense_w,  const float* __restrict__ dense_b,
    float* __restrict__ out)
{
    const int t = threadIdx.x;
    int badl = g_badv[t];
    if (!__syncthreads_or(badl)) return;

    __shared__ float v0s[UNITS], v1s[UNITS], sx[SENS];
    const int b = blockIdx.x;
    const int j = t;
    float cmt = cm[j] * (float)UNF, gl = gleak[j], gv = gl * vleak[j];
    v0s[j] = 0.f;
    __syncthreads();
    float* cur = v0s; float* nxt = v1s;
    for (int s = 0; s < NT; s++) {
        if (t < SENS)
            sx[t] = fmaf(inputs[(b * NT + s) * SENS + t], input_w[t], input_b[t]);
        __syncthreads();
        float sn = 0.f, sd = 0.f;
        for (int i = 0; i < SENS; i++) {
            float m = smask[i * UNITS + j];
            if (m != 0.f) {
                float sg = ssig[i * UNITS + j];
                float sv = rcpf(1.f + ex2f(LOG2E * sg * (smu[i * UNITS + j] - sx[i])));
                float wm = swt[i * UNITS + j] * m;
                sd += wm * sv; sn += wm * serev[i * UNITS + j] * sv;
            }
        }
        for (int u = 0; u < UNF; u++) {
            float na = sn, da = sd;
            for (int i = 0; i < UNITS; i++) {
                float m = mask[i * UNITS + j];
                if (m != 0.f) {
                    float sg = sig[i * UNITS + j];
                    float sv = rcpf(1.f + ex2f(LOG2E * sg * (mu[i * UNITS + j] - cur[i])));
                    float wm = wt[i * UNITS + j] * m;
                    da += wm * sv; na += wm * erev[i * UNITS + j] * sv;
                }
            }
            nxt[j] = (fmaf(cmt, cur[j], gv) + na) * rcpf(cmt + gl + da + EPSF);
            __syncthreads();
            float* tmp = cur; cur = nxt; nxt = tmp;
        }
        if (t < OUTL) {
            float acc = dense_b[t];
            for (int m = 0; m < MOTORN; m++)
                acc = fmaf(fmaf(cur[m], output_w[m], output_b[m]),
                           dense_w[m * OUTL + t], acc);
            out[(b * NT + s) * OUTL + t] = acc;
        }
        __syncthreads();
    }
}

extern "C" void kernel_launch(void* const* d_in, const int* in_sizes, int n_in,
                              void* d_out, int out_size)
{
    const float* inputs   = (const float*)d_in[0];
    const float* input_w  = (const float*)d_in[1];
    const float* input_b  = (const float*)d_in[2];
    const float* smu      = (const float*)d_in[3];
    const float* ssig     = (const float*)d_in[4];
    const float* swt      = (const float*)d_in[5];
    const float* serev    = (const float*)d_in[6];
    const float* smask    = (const float*)d_in[7];
    const float* mu       = (const float*)d_in[8];
    const float* sig      = (const float*)d_in[9];
    const float* wt       = (const float*)d_in[10];
    const float* erev     = (const float*)d_in[11];
    const float* mask     = (const float*)d_in[12];
    const float* gleak    = (const float*)d_in[13];
    const float* vleak    = (const float*)d_in[14];
    const float* cm       = (const float*)d_in[15];
    const float* output_w = (const float*)d_in[16];
    const float* output_b = (const float*)d_in[17];
    const float* dense_w  = (const float*)d_in[18];
    const float* dense_b  = (const float*)d_in[19];
    float* out = (float*)d_out;

    kprep<<<UNITS, 32>>>(smu, ssig, swt, serev, smask, mu, sig, wt, erev, mask);
    kp1<<<NB * NT, 256>>>(inputs, input_w, input_b, gleak, vleak, cm);
    kiscan<<<NB, INTERN>>>();
    kp2<<<NB * NT, 256>>>();
    kp3<<<NB, 32>>>(gleak, vleak, cm);
    kp4<<<NB * NT, 256>>>(gleak, vleak, cm);
    kp5<<<8, 128>>>(output_w, output_b, dense_w, dense_b, out);
    kfall<<<NB, UNITS>>>(inputs, input_w, input_b,
                         smu, ssig, swt, serev, smask,
                         mu, sig, wt, erev, mask,
                         gleak, vleak, cm,
                         output_w, output_b, dense_w, dense_b, out);
}